// round 2
// baseline (speedup 1.0000x reference)
#include <cuda_runtime.h>
#include <math.h>

#define BB 16
#define HH 256
#define WW 256
#define CC 32
#define EM0 16
#define EM1 17
#define NROW 32   /* 2*EM0 kept rows */

// scratch (static device globals; no runtime allocation)
__device__ float2 g_tw[256];
__device__ float2 g_A[(size_t)BB * HH * EM1 * CC];   // after W-DFT   (17.8 MB)
__device__ float2 g_X[(size_t)BB * NROW * EM1 * CC]; // after H-DFT   (2.2 MB)
__device__ float2 g_Y[(size_t)BB * NROW * EM1 * CC]; // after mix     (2.2 MB)
__device__ float2 g_Z[(size_t)BB * HH * EM1 * CC];   // after H-inv   (17.8 MB)

// ---------------- K0: twiddle table  tw[k] = (cos, sin)(2*pi*k/256) ----------------
__global__ void k0_tw() {
    int t = threadIdx.x;
    float s, c;
    sincospif((float)t / 128.0f, &s, &c);
    g_tw[t] = make_float2(c, s);
}

// ---------------- K1: W-DFT, 256 -> 17 bins, folded (w, 256-w) ----------------
// A[b,h,kw,ci] = (1/65536) * sum_w x[b,h,w,ci] e^{-2pi i kw w/256}
__global__ void __launch_bounds__(128) k1_wdft(const float* __restrict__ x) {
    __shared__ float sU[128][CC];
    __shared__ float sV[128][CC];
    __shared__ float2 sT[256];
    int row = blockIdx.x;            // b*H + h
    int tid = threadIdx.x;           // 128
    for (int i = tid; i < 256; i += 128) sT[i] = g_tw[i];
    const float* xr = x + (size_t)row * (WW * CC);
    for (int idx = tid; idx < 128 * CC; idx += 128) {
        int w = idx >> 5, ci = idx & 31;
        if (w == 0) {
            sU[0][ci] = xr[ci];              // x0
            sV[0][ci] = xr[128 * CC + ci];   // x128
        } else {
            float a  = xr[w * CC + ci];
            float b2 = xr[(256 - w) * CC + ci];
            sU[w][ci] = a + b2;
            sV[w][ci] = a - b2;
        }
    }
    __syncthreads();
    int warp = tid >> 5, ci = tid & 31;
    int kw0 = warp * 4;
    int nk = (warp == 3) ? 5 : 4;    // warp3 covers kw 12..16
    float aR[5] = {0.f,0.f,0.f,0.f,0.f};
    float aI[5] = {0.f,0.f,0.f,0.f,0.f};
    for (int w = 1; w < 128; w++) {
        float u = sU[w][ci], v = sV[w][ci];
#pragma unroll
        for (int j = 0; j < 5; j++) {
            if (j < nk) {
                float2 t = sT[((kw0 + j) * w) & 255];
                aR[j] += u * t.x;
                aI[j] -= v * t.y;
            }
        }
    }
    float x0 = sU[0][ci], x128 = sV[0][ci];
    const float scale = 1.0f / 65536.0f;
#pragma unroll
    for (int j = 0; j < 5; j++) {
        if (j < nk) {
            int kw = kw0 + j;
            float re = aR[j] + x0 + ((kw & 1) ? -x128 : x128);
            g_A[((size_t)row * EM1 + kw) * CC + ci] = make_float2(re * scale, aI[j] * scale);
        }
    }
}

// ---------------- K2: H-DFT at the 32 kept rows ----------------
// X[b,j,kw,ci] = sum_h A[b,h,kw,ci] e^{-2pi i kh(j) h/256},  kh(j)= j<16 ? j : 224+j
extern __shared__ float2 k2smem[];
__global__ void __launch_bounds__(256) k2_hdft() {
    float2 (*sA)[CC] = (float2(*)[CC])k2smem;   // 256 x 32 complex = 64KB
    float2* sT = k2smem + 256 * CC;
    int b = blockIdx.x / EM1, kw = blockIdx.x % EM1;
    int tid = threadIdx.x;   // 256
    sT[tid] = g_tw[tid];
    for (int idx = tid; idx < 256 * CC; idx += 256) {
        int h = idx >> 5, ci = idx & 31;
        sA[h][ci] = g_A[(((size_t)b * HH + h) * EM1 + kw) * CC + ci];
    }
    __syncthreads();
    for (int oi = tid; oi < NROW * CC; oi += 256) {
        int j = oi >> 5, ci = oi & 31;
        int kh = (j < EM0) ? j : 224 + j;
        float aR = 0.f, aI = 0.f;
        for (int h = 0; h < 256; h++) {
            float2 a = sA[h][ci];
            float2 t = sT[(kh * h) & 255];
            aR += a.x * t.x + a.y * t.y;   // (ar+i ai)(c - i s)
            aI += a.y * t.x - a.x * t.y;
        }
        g_X[(((size_t)b * NROW + j) * EM1 + kw) * CC + ci] = make_float2(aR, aI);
    }
}

// ---------------- K3: per-mode 32x32 complex channel mixing ----------------
__global__ void __launch_bounds__(256) k3_mix(const float* __restrict__ w1r,
                                              const float* __restrict__ w1i,
                                              const float* __restrict__ w2r,
                                              const float* __restrict__ w2i) {
    __shared__ float2 sW[CC][CC];
    __shared__ float2 sX[BB][CC];
    int j = blockIdx.x / EM1, kw = blockIdx.x % EM1;
    int tid = threadIdx.x;  // 256
    const float* wr; const float* wi; int hh;
    if (j < EM0) { wr = w1r; wi = w1i; hh = j; }
    else         { wr = w2r; wi = w2i; hh = j - EM0; }
    for (int idx = tid; idx < CC * CC; idx += 256) {
        int ci = idx >> 5, co = idx & 31;
        int off = ((ci * CC + co) * EM0 + hh) * EM1 + kw;
        sW[ci][co] = make_float2(wr[off], wi[off]);
    }
    for (int idx = tid; idx < BB * CC; idx += 256) {
        int bb = idx >> 5, ci = idx & 31;
        sX[bb][ci] = g_X[(((size_t)bb * NROW + j) * EM1 + kw) * CC + ci];
    }
    __syncthreads();
    int bb = tid >> 5, co = tid & 31;
#pragma unroll
    for (int bstep = 0; bstep < 2; bstep++) {
        int bcur = bb + bstep * 8;
        float yR = 0.f, yI = 0.f;
#pragma unroll
        for (int ci = 0; ci < CC; ci++) {
            float2 xv = sX[bcur][ci];
            float2 wv = sW[ci][co];
            yR += xv.x * wv.x - xv.y * wv.y;
            yI += xv.x * wv.y + xv.y * wv.x;
        }
        g_Y[(((size_t)bcur * NROW + j) * EM1 + kw) * CC + co] = make_float2(yR, yI);
    }
}

// ---------------- K4: H-inverse, 32 kept rows -> 256 h ----------------
// Z[b,h,kw,co] = sum_j Y[b,j,kw,co] e^{+2pi i kh(j) h/256}
__global__ void __launch_bounds__(256) k4_hinv() {
    __shared__ float2 sY[NROW][CC];
    __shared__ float2 sT[256];
    int b = blockIdx.x / EM1, kw = blockIdx.x % EM1;
    int tid = threadIdx.x;
    sT[tid] = g_tw[tid];
    for (int idx = tid; idx < NROW * CC; idx += 256) {
        int j = idx >> 5, co = idx & 31;
        sY[j][co] = g_Y[(((size_t)b * NROW + j) * EM1 + kw) * CC + co];
    }
    __syncthreads();
    int co = tid & 31, hb = tid >> 5;
    for (int h = hb; h < 256; h += 8) {
        float zR = 0.f, zI = 0.f;
#pragma unroll
        for (int j = 0; j < NROW; j++) {
            int kh = (j < EM0) ? j : 224 + j;
            float2 y = sY[j][co];
            float2 t = sT[(kh * h) & 255];
            zR += y.x * t.x - y.y * t.y;   // (yr+i yi)(c + i s)
            zI += y.x * t.y + y.y * t.x;
        }
        g_Z[(((size_t)b * HH + h) * EM1 + kw) * CC + co] = make_float2(zR, zI);
    }
}

// ---------------- K5: W-inverse (17 bins -> 256), folded, + bias ----------------
// y[w] = Re z0 + 2*sum_{kw=1..16}(zr c - zi s) + bias ;  y[256-w] flips the sin sign
__global__ void __launch_bounds__(256) k5_winv(const float* __restrict__ bias,
                                               float* __restrict__ out) {
    __shared__ float2 sZ[EM1][CC];
    __shared__ float2 sT[256];
    __shared__ float sB[CC];
    int row = blockIdx.x;          // b*H + h
    int tid = threadIdx.x;         // 256
    sT[tid] = g_tw[tid];
    if (tid < CC) sB[tid] = bias[tid];
    for (int idx = tid; idx < EM1 * CC; idx += 256) {
        int kw = idx >> 5, co = idx & 31;
        sZ[kw][co] = g_Z[((size_t)row * EM1 + kw) * CC + co];
    }
    __syncthreads();
    int co = tid & 31, wb = tid >> 5;   // wb 0..7
    float zr[16], zi[16];
#pragma unroll
    for (int k = 0; k < 16; k++) {
        float2 z = sZ[k + 1][co];
        zr[k] = z.x; zi[k] = z.y;
    }
    float base = sZ[0][co].x + sB[co];   // Im(z0) discarded (irfft半complex semantics)
    float* orow = out + (size_t)row * (WW * CC);
    for (int m = 0; m < 16; m++) {
        int w = wb + 8 * m;              // covers 0..127
        float P = 0.f, Q = 0.f;
#pragma unroll
        for (int k = 0; k < 16; k++) {
            float2 t = sT[((k + 1) * w) & 255];
            P += zr[k] * t.x;
            Q += zi[k] * t.y;
        }
        if (w == 0) {
            orow[co] = base + 2.0f * P;                 // Q=0 at w=0
            float alt = 0.f;
#pragma unroll
            for (int k = 0; k < 16; k++) alt += (((k + 1) & 1) ? -zr[k] : zr[k]);
            orow[128 * CC + co] = base + 2.0f * alt;    // w = 128 (Nyquist of fold)
        } else {
            orow[w * CC + co]         = base + 2.0f * (P - Q);
            orow[(256 - w) * CC + co] = base + 2.0f * (P + Q);
        }
    }
}

extern "C" void kernel_launch(void* const* d_in, const int* in_sizes, int n_in,
                              void* d_out, int out_size) {
    const float* x    = (const float*)d_in[0];
    const float* w1r  = (const float*)d_in[1];
    const float* w1i  = (const float*)d_in[2];
    const float* w2r  = (const float*)d_in[3];
    const float* w2i  = (const float*)d_in[4];
    const float* bias = (const float*)d_in[5];
    float* out = (float*)d_out;

    k0_tw<<<1, 256>>>();
    k1_wdft<<<BB * HH, 128>>>(x);

    size_t k2smem_bytes = (256 * CC + 256) * sizeof(float2);   // 66 KB
    cudaFuncSetAttribute(k2_hdft, cudaFuncAttributeMaxDynamicSharedMemorySize,
                         (int)k2smem_bytes);
    k2_hdft<<<BB * EM1, 256, k2smem_bytes>>>();

    k3_mix<<<NROW * EM1, 256>>>(w1r, w1i, w2r, w2i);
    k4_hinv<<<BB * EM1, 256>>>();
    k5_winv<<<BB * HH, 256>>>(bias, out);
}

// round 3
// speedup vs baseline: 1.0977x; 1.0977x over previous
#include <cuda_runtime.h>
#include <math.h>

#define BB 16
#define HH 256
#define WW 256
#define CC 32
#define EM0 16
#define EM1 17
#define NROW 32   /* 2*EM0 kept rows */

// scratch (static device globals; no runtime allocation)
__device__ float2 g_tw[256];
__device__ float2 g_A[(size_t)BB * EM1 * HH * CC];    // A_t[b,kw][h][ci]
__device__ float2 g_X[(size_t)NROW * EM1 * BB * CC];  // X_t[j,kw][b][ci]
__device__ float2 g_Y[(size_t)BB * EM1 * NROW * CC];  // Y_t[b,kw][j][co]
__device__ float2 g_Z[(size_t)BB * HH * EM1 * CC];    // Z[row][kw][co]
__device__ float2 g_Wt[(size_t)NROW * EM1 * CC * CC]; // W_t[j,kw][ci][co]

// ---------------- K0: twiddle table  tw[k] = (cos, sin)(2*pi*k/256) ----------------
__global__ void k0_tw() {
    int t = threadIdx.x;
    float s, c;
    sincospif((float)t / 128.0f, &s, &c);
    g_tw[t] = make_float2(c, s);
}

// ---------------- Kt: weight transpose into [j,kw][ci][co] float2 ----------------
__global__ void kt_w(const float* __restrict__ w1r, const float* __restrict__ w1i,
                     const float* __restrict__ w2r, const float* __restrict__ w2i) {
    int t = blockIdx.x * 256 + threadIdx.x;
    if (t >= CC * CC * EM0 * EM1) return;
    int kw = t % EM1; int r = t / EM1;
    int hh = r & 15;  r >>= 4;
    int co = r & 31;  int ci = r >> 5;
    g_Wt[((size_t)(hh * EM1 + kw)) * 1024 + ci * 32 + co] = make_float2(w1r[t], w1i[t]);
    g_Wt[((size_t)((hh + 16) * EM1 + kw)) * 1024 + ci * 32 + co] = make_float2(w2r[t], w2i[t]);
}

// ---------------- K1: W-DFT, 256 -> 17 bins, folded (w, 256-w) ----------------
// A[b,kw][h][ci] = (1/65536) * sum_w x[b,h,w,ci] e^{-2pi i kw w/256}
__global__ void __launch_bounds__(128) k1_wdft(const float* __restrict__ x) {
    __shared__ float sU[128][32];
    __shared__ float sV[128][32];
    __shared__ float2 sT[256];
    int row = blockIdx.x;            // b*H + h
    int tid = threadIdx.x;
    for (int i = tid; i < 256; i += 128) sT[i] = g_tw[i];
    const float4* x4 = (const float4*)(x + (size_t)row * 8192);
    float4* sU4 = (float4*)sU;
    float4* sV4 = (float4*)sV;
    for (int idx = tid; idx < 1024; idx += 128) {
        int w = idx >> 3, cg = idx & 7;
        float4 a = x4[w * 8 + cg];
        if (w == 0) {
            sU4[cg] = a;                      // x0
            sV4[cg] = x4[128 * 8 + cg];       // x128
        } else {
            float4 b = x4[(256 - w) * 8 + cg];
            sU4[w * 8 + cg] = make_float4(a.x + b.x, a.y + b.y, a.z + b.z, a.w + b.w);
            sV4[w * 8 + cg] = make_float4(a.x - b.x, a.y - b.y, a.z - b.z, a.w - b.w);
        }
    }
    __syncthreads();
    int lane = tid & 31, warp = tid >> 5;
    int cig = lane & 7, kwsub = lane >> 3;
    int kw = warp * 4 + kwsub + 1;          // 1..16
    bool do0 = (tid < 8);                   // these lanes also accumulate kw=0
    float R[4] = {0, 0, 0, 0}, I[4] = {0, 0, 0, 0}, R0[4] = {0, 0, 0, 0};
    int tIdx = kw & 255;
    const float4* U = sU4 + cig;
    const float4* V = sV4 + cig;
#pragma unroll 4
    for (int w = 1; w < 128; w++) {
        float4 u = U[w * 8];
        float4 v = V[w * 8];
        float2 t = sT[tIdx];
        tIdx = (tIdx + kw) & 255;
        R[0] += u.x * t.x; R[1] += u.y * t.x; R[2] += u.z * t.x; R[3] += u.w * t.x;
        I[0] -= v.x * t.y; I[1] -= v.y * t.y; I[2] -= v.z * t.y; I[3] -= v.w * t.y;
        if (do0) { R0[0] += u.x; R0[1] += u.y; R0[2] += u.z; R0[3] += u.w; }
    }
    int ci0 = cig * 4;
    float x0c[4], x1c[4];
#pragma unroll
    for (int c = 0; c < 4; c++) { x0c[c] = sU[0][ci0 + c]; x1c[c] = sV[0][ci0 + c]; }
    const float S = 1.0f / 65536.0f;
    float sgn = (kw & 1) ? -1.0f : 1.0f;
    int b = row >> 8, h = row & 255;
    {
        float2 o[4];
#pragma unroll
        for (int c = 0; c < 4; c++)
            o[c] = make_float2((R[c] + x0c[c] + sgn * x1c[c]) * S, I[c] * S);
        float4* dst = (float4*)(g_A + (((size_t)(b * EM1 + kw)) * HH + h) * CC + ci0);
        dst[0] = make_float4(o[0].x, o[0].y, o[1].x, o[1].y);
        dst[1] = make_float4(o[2].x, o[2].y, o[3].x, o[3].y);
    }
    if (do0) {
        float2 o[4];
#pragma unroll
        for (int c = 0; c < 4; c++)
            o[c] = make_float2((R0[c] + x0c[c] + x1c[c]) * S, 0.0f);
        float4* dst = (float4*)(g_A + (((size_t)(b * EM1 + 0)) * HH + h) * CC + ci0);
        dst[0] = make_float4(o[0].x, o[0].y, o[1].x, o[1].y);
        dst[1] = make_float4(o[2].x, o[2].y, o[3].x, o[3].y);
    }
}

// ---------------- K2: H-DFT at the 32 kept rows ----------------
// X[j,kw][b][ci] = sum_h A[b,kw][h][ci] e^{-2pi i kh(j) h/256}
extern __shared__ float2 k2smem[];
__global__ void __launch_bounds__(128) k2_hdft() {
    float2* sA = k2smem;              // 256*32 float2 = 64KB
    float2* sT = k2smem + 8192;       // 256
    int b = blockIdx.x / EM1, kw = blockIdx.x % EM1;
    int tid = threadIdx.x;
    const float4* src = (const float4*)(g_A + ((size_t)(b * EM1 + kw)) * HH * CC);
    float4* sA4 = (float4*)sA;
    for (int i = tid; i < 4096; i += 128) sA4[i] = src[i];
    for (int i = tid; i < 256; i += 128) sT[i] = g_tw[i];
    __syncthreads();
    int cig = tid & 7, jg = tid >> 3;   // jg 0..15
    int ci0 = cig * 4;
    int kh_a = jg;                      // j = jg      -> kh = jg
    int kh_b = 240 + jg;                // j = jg+16   -> kh = 224 + jg + 16
    float aRa[4] = {0,0,0,0}, aIa[4] = {0,0,0,0};
    float aRb[4] = {0,0,0,0}, aIb[4] = {0,0,0,0};
    int ia = 0, ib = 0;
    for (int h = 0; h < 256; h++) {
        const float4* arow = (const float4*)(sA + h * 32 + ci0);
        float4 p0 = arow[0];
        float4 p1 = arow[1];
        float2 ta = sT[ia]; float2 tb = sT[ib];
        ia = (ia + kh_a) & 255; ib = (ib + kh_b) & 255;
        aRa[0] += p0.x * ta.x + p0.y * ta.y;  aIa[0] += p0.y * ta.x - p0.x * ta.y;
        aRa[1] += p0.z * ta.x + p0.w * ta.y;  aIa[1] += p0.w * ta.x - p0.z * ta.y;
        aRa[2] += p1.x * ta.x + p1.y * ta.y;  aIa[2] += p1.y * ta.x - p1.x * ta.y;
        aRa[3] += p1.z * ta.x + p1.w * ta.y;  aIa[3] += p1.w * ta.x - p1.z * ta.y;
        aRb[0] += p0.x * tb.x + p0.y * tb.y;  aIb[0] += p0.y * tb.x - p0.x * tb.y;
        aRb[1] += p0.z * tb.x + p0.w * tb.y;  aIb[1] += p0.w * tb.x - p0.z * tb.y;
        aRb[2] += p1.x * tb.x + p1.y * tb.y;  aIb[2] += p1.y * tb.x - p1.x * tb.y;
        aRb[3] += p1.z * tb.x + p1.w * tb.y;  aIb[3] += p1.w * tb.x - p1.z * tb.y;
    }
    {
        float4* dst = (float4*)(g_X + (((size_t)(jg * EM1 + kw)) * BB + b) * CC + ci0);
        dst[0] = make_float4(aRa[0], aIa[0], aRa[1], aIa[1]);
        dst[1] = make_float4(aRa[2], aIa[2], aRa[3], aIa[3]);
    }
    {
        float4* dst = (float4*)(g_X + (((size_t)((jg + 16) * EM1 + kw)) * BB + b) * CC + ci0);
        dst[0] = make_float4(aRb[0], aIb[0], aRb[1], aIb[1]);
        dst[1] = make_float4(aRb[2], aIb[2], aRb[3], aIb[3]);
    }
}

// ---------------- K3: per-mode 32x32 complex channel mixing ----------------
__global__ void __launch_bounds__(128) k3_mix() {
    __shared__ float2 sW[1024];   // [ci][co]
    __shared__ float2 sX[512];    // [b][ci]
    int j = blockIdx.x / EM1, kw = blockIdx.x % EM1;
    int tid = threadIdx.x;
    const float4* wsrc = (const float4*)(g_Wt + ((size_t)(j * EM1 + kw)) * 1024);
    float4* sW4 = (float4*)sW;
    for (int i = tid; i < 512; i += 128) sW4[i] = wsrc[i];
    const float4* xsrc = (const float4*)(g_X + ((size_t)(j * EM1 + kw)) * BB * CC);
    float4* sX4 = (float4*)sX;
    for (int i = tid; i < 256; i += 128) sX4[i] = xsrc[i];
    __syncthreads();
    int co = tid & 31, bg = tid >> 5;
    float yR[4] = {0,0,0,0}, yI[4] = {0,0,0,0};
#pragma unroll 8
    for (int ci = 0; ci < 32; ci++) {
        float2 wv = sW[ci * 32 + co];
#pragma unroll
        for (int s = 0; s < 4; s++) {
            float2 xv = sX[(bg * 4 + s) * 32 + ci];
            yR[s] += xv.x * wv.x - xv.y * wv.y;
            yI[s] += xv.x * wv.y + xv.y * wv.x;
        }
    }
#pragma unroll
    for (int s = 0; s < 4; s++) {
        int b = bg * 4 + s;
        g_Y[(((size_t)(b * EM1 + kw)) * NROW + j) * CC + co] = make_float2(yR[s], yI[s]);
    }
}

// ---------------- K4: H-inverse, 32 kept rows -> 256 h ----------------
// Z[row][kw][co] = sum_j Y[b,kw][j][co] e^{+2pi i kh(j) h/256}
__global__ void __launch_bounds__(128) k4_hinv() {
    __shared__ float2 sY[1024];   // [j][co]
    __shared__ float2 sT[256];
    int b = blockIdx.x / EM1, kw = blockIdx.x % EM1;
    int tid = threadIdx.x;
    const float4* src = (const float4*)(g_Y + ((size_t)(b * EM1 + kw)) * NROW * CC);
    float4* sY4 = (float4*)sY;
    for (int i = tid; i < 512; i += 128) sY4[i] = src[i];
    for (int i = tid; i < 256; i += 128) sT[i] = g_tw[i];
    __syncthreads();
    int cig = tid & 7, hg = tid >> 3;
    int ci0 = cig * 4;
    for (int m = 0; m < 4; m++) {
        int h0 = hg + 64 * m;     // h_i = h0 + 16*i
        float zR[4][4], zI[4][4];
#pragma unroll
        for (int i = 0; i < 4; i++)
#pragma unroll
            for (int c = 0; c < 4; c++) { zR[i][c] = 0.0f; zI[i][c] = 0.0f; }
#pragma unroll
        for (int j = 0; j < 32; j++) {
            const int kh = (j < 16) ? j : 224 + j;
            const float4* yrow = (const float4*)(sY + j * 32 + ci0);
            float4 p0 = yrow[0];
            float4 p1 = yrow[1];
#pragma unroll
            for (int i = 0; i < 4; i++) {
                float2 t = sT[(kh * (h0 + 16 * i)) & 255];
                zR[i][0] += p0.x * t.x - p0.y * t.y;  zI[i][0] += p0.x * t.y + p0.y * t.x;
                zR[i][1] += p0.z * t.x - p0.w * t.y;  zI[i][1] += p0.z * t.y + p0.w * t.x;
                zR[i][2] += p1.x * t.x - p1.y * t.y;  zI[i][2] += p1.x * t.y + p1.y * t.x;
                zR[i][3] += p1.z * t.x - p1.w * t.y;  zI[i][3] += p1.z * t.y + p1.w * t.x;
            }
        }
#pragma unroll
        for (int i = 0; i < 4; i++) {
            int row = b * 256 + h0 + 16 * i;
            float4* dst = (float4*)(g_Z + ((size_t)row * EM1 + kw) * CC + ci0);
            dst[0] = make_float4(zR[i][0], zI[i][0], zR[i][1], zI[i][1]);
            dst[1] = make_float4(zR[i][2], zI[i][2], zR[i][3], zI[i][3]);
        }
    }
}

// ---------------- K5: W-inverse (17 bins -> 256), folded, + bias ----------------
__global__ void __launch_bounds__(128) k5_winv(const float* __restrict__ bias,
                                               float* __restrict__ out) {
    __shared__ float2 sZ[EM1 * 32];
    __shared__ float2 sT[256];
    __shared__ float sB[32];
    int row = blockIdx.x;
    int tid = threadIdx.x;
    const float4* src = (const float4*)(g_Z + (size_t)row * EM1 * CC);
    float4* sZ4 = (float4*)sZ;
    for (int i = tid; i < 272; i += 128) sZ4[i] = src[i];
    for (int i = tid; i < 256; i += 128) sT[i] = g_tw[i];
    if (tid < 32) sB[tid] = bias[tid];
    __syncthreads();
    int cig = tid & 7, wg = tid >> 3;
    int ci0 = cig * 4;
    float base[4];
#pragma unroll
    for (int c = 0; c < 4; c++) base[c] = sZ[ci0 + c].x + sB[ci0 + c];
    float* orow = out + (size_t)row * 8192;
#pragma unroll
    for (int m = 0; m < 4; m++) {
        int wa = wg + 32 * m, wb = wg + 16 + 32 * m;
        float Pa[4] = {0,0,0,0}, Qa[4] = {0,0,0,0};
        float Pb[4] = {0,0,0,0}, Qb[4] = {0,0,0,0};
        int ja = wa & 255, jb = wb & 255;
#pragma unroll
        for (int k = 0; k < 16; k++) {
            const float4* zrow = (const float4*)(sZ + (k + 1) * 32 + ci0);
            float4 p0 = zrow[0];
            float4 p1 = zrow[1];
            float2 ta = sT[ja]; float2 tb = sT[jb];
            ja = (ja + wa) & 255; jb = (jb + wb) & 255;
            Pa[0] += p0.x * ta.x; Qa[0] += p0.y * ta.y;
            Pa[1] += p0.z * ta.x; Qa[1] += p0.w * ta.y;
            Pa[2] += p1.x * ta.x; Qa[2] += p1.y * ta.y;
            Pa[3] += p1.z * ta.x; Qa[3] += p1.w * ta.y;
            Pb[0] += p0.x * tb.x; Qb[0] += p0.y * tb.y;
            Pb[1] += p0.z * tb.x; Qb[1] += p0.w * tb.y;
            Pb[2] += p1.x * tb.x; Qb[2] += p1.y * tb.y;
            Pb[3] += p1.z * tb.x; Qb[3] += p1.w * tb.y;
        }
        if (wa == 0) {
            *(float4*)(orow + ci0) = make_float4(
                base[0] + 2.0f * Pa[0], base[1] + 2.0f * Pa[1],
                base[2] + 2.0f * Pa[2], base[3] + 2.0f * Pa[3]);
            float alt[4] = {0,0,0,0};
#pragma unroll
            for (int k = 0; k < 16; k++) {
                const float2* zr = sZ + (k + 1) * 32 + ci0;
                float s = ((k + 1) & 1) ? -1.0f : 1.0f;
#pragma unroll
                for (int c = 0; c < 4; c++) alt[c] += s * zr[c].x;
            }
            *(float4*)(orow + 128 * 32 + ci0) = make_float4(
                base[0] + 2.0f * alt[0], base[1] + 2.0f * alt[1],
                base[2] + 2.0f * alt[2], base[3] + 2.0f * alt[3]);
        } else {
            *(float4*)(orow + wa * 32 + ci0) = make_float4(
                base[0] + 2.0f * (Pa[0] - Qa[0]), base[1] + 2.0f * (Pa[1] - Qa[1]),
                base[2] + 2.0f * (Pa[2] - Qa[2]), base[3] + 2.0f * (Pa[3] - Qa[3]));
            *(float4*)(orow + (256 - wa) * 32 + ci0) = make_float4(
                base[0] + 2.0f * (Pa[0] + Qa[0]), base[1] + 2.0f * (Pa[1] + Qa[1]),
                base[2] + 2.0f * (Pa[2] + Qa[2]), base[3] + 2.0f * (Pa[3] + Qa[3]));
        }
        *(float4*)(orow + wb * 32 + ci0) = make_float4(
            base[0] + 2.0f * (Pb[0] - Qb[0]), base[1] + 2.0f * (Pb[1] - Qb[1]),
            base[2] + 2.0f * (Pb[2] - Qb[2]), base[3] + 2.0f * (Pb[3] - Qb[3]));
        *(float4*)(orow + (256 - wb) * 32 + ci0) = make_float4(
            base[0] + 2.0f * (Pb[0] + Qb[0]), base[1] + 2.0f * (Pb[1] + Qb[1]),
            base[2] + 2.0f * (Pb[2] + Qb[2]), base[3] + 2.0f * (Pb[3] + Qb[3]));
    }
}

extern "C" void kernel_launch(void* const* d_in, const int* in_sizes, int n_in,
                              void* d_out, int out_size) {
    const float* x    = (const float*)d_in[0];
    const float* w1r  = (const float*)d_in[1];
    const float* w1i  = (const float*)d_in[2];
    const float* w2r  = (const float*)d_in[3];
    const float* w2i  = (const float*)d_in[4];
    const float* bias = (const float*)d_in[5];
    float* out = (float*)d_out;

    k0_tw<<<1, 256>>>();
    kt_w<<<1088, 256>>>(w1r, w1i, w2r, w2i);
    k1_wdft<<<BB * HH, 128>>>(x);

    size_t k2smem_bytes = (8192 + 256) * sizeof(float2);   // 67584 B
    cudaFuncSetAttribute(k2_hdft, cudaFuncAttributeMaxDynamicSharedMemorySize,
                         (int)k2smem_bytes);
    k2_hdft<<<BB * EM1, 128, k2smem_bytes>>>();

    k3_mix<<<NROW * EM1, 128>>>();
    k4_hinv<<<BB * EM1, 128>>>();
    k5_winv<<<BB * HH, 128>>>(bias, out);
}

// round 4
// speedup vs baseline: 1.8907x; 1.7225x over previous
#include <cuda_runtime.h>
#include <math.h>

#define BB 16
#define HH 256
#define WW 256
#define CC 32
#define EM0 16
#define EM1 17
#define NROW 32

__device__ float2 g_tw[256];
__device__ float2 g_A[(size_t)BB * EM1 * HH * CC];    // A[b,kw][h][ci]
__device__ float2 g_X[(size_t)NROW * EM1 * BB * CC];  // X[j,kw][b][ci]
__device__ float2 g_Y[(size_t)BB * EM1 * NROW * CC];  // Y[b,kw][j][co]
__device__ float2 g_Z[(size_t)BB * HH * EM1 * CC];    // Z[row][kw][co]
__device__ float2 g_Wt[(size_t)NROW * EM1 * CC * CC]; // W[j,kw][ci][co]

// ---------------- K0: twiddles tw[k] = (cos,sin)(2*pi*k/256) ----------------
__global__ void k0_tw() {
    int t = threadIdx.x;
    float s, c;
    sincospif((float)t / 128.0f, &s, &c);
    g_tw[t] = make_float2(c, s);
}

// ---------------- Kt: weight transpose ----------------
__global__ void kt_w(const float* __restrict__ w1r, const float* __restrict__ w1i,
                     const float* __restrict__ w2r, const float* __restrict__ w2i) {
    int t = blockIdx.x * 256 + threadIdx.x;
    if (t >= CC * CC * EM0 * EM1) return;
    int kw = t % EM1; int r = t / EM1;
    int hh = r & 15;  r >>= 4;
    int co = r & 31;  int ci = r >> 5;
    g_Wt[((size_t)(hh * EM1 + kw)) * 1024 + ci * 32 + co] = make_float2(w1r[t], w1i[t]);
    g_Wt[((size_t)((hh + 16) * EM1 + kw)) * 1024 + ci * 32 + co] = make_float2(w2r[t], w2i[t]);
}

// ---------------- K1: W-DFT 256 -> 17 bins, folded ----------------
__global__ void __launch_bounds__(128) k1_wdft(const float* __restrict__ x) {
    __shared__ __align__(16) float sU[128][32];
    __shared__ __align__(16) float sV[128][32];
    __shared__ float2 sT[256];
    __shared__ float sRed[4][32];
    int row = blockIdx.x;
    int tid = threadIdx.x;
    for (int i = tid; i < 256; i += 128) sT[i] = g_tw[i];
    const float4* x4 = (const float4*)(x + (size_t)row * 8192);
    float4* sU4 = (float4*)sU;
    float4* sV4 = (float4*)sV;
    for (int idx = tid; idx < 1024; idx += 128) {
        int w = idx >> 3, cg = idx & 7;
        float4 a = x4[w * 8 + cg];
        if (w == 0) {
            sU4[cg] = a;
            sV4[cg] = x4[128 * 8 + cg];
        } else {
            float4 b = x4[(256 - w) * 8 + cg];
            sU4[w * 8 + cg] = make_float4(a.x + b.x, a.y + b.y, a.z + b.z, a.w + b.w);
            sV4[w * 8 + cg] = make_float4(a.x - b.x, a.y - b.y, a.z - b.z, a.w - b.w);
        }
    }
    __syncthreads();
    int lane = tid & 31, warp = tid >> 5;
    int cig = lane & 7, kwsub = lane >> 3;
    int kw = warp * 4 + kwsub + 1;         // 1..16
    float R[4] = {0, 0, 0, 0}, I[4] = {0, 0, 0, 0};
    int tIdx = kw;
    const float4* U = sU4 + cig;
    const float4* V = sV4 + cig;
#pragma unroll 4
    for (int w = 1; w < 128; w++) {
        float4 u = U[w * 8];
        float4 v = V[w * 8];
        float2 t = sT[tIdx];
        tIdx = (tIdx + kw) & 255;
        R[0] += u.x * t.x; R[1] += u.y * t.x; R[2] += u.z * t.x; R[3] += u.w * t.x;
        I[0] -= v.x * t.y; I[1] -= v.y * t.y; I[2] -= v.z * t.y; I[3] -= v.w * t.y;
    }
    const float S = 1.0f / 65536.0f;
    int ci0 = cig * 4;
    int b = row >> 8, h = row & 255;
    {
        float sgn = (kw & 1) ? -1.0f : 1.0f;
        float2 o[4];
#pragma unroll
        for (int c = 0; c < 4; c++) {
            float re = R[c] + sU[0][ci0 + c] + sgn * sV[0][ci0 + c];
            o[c] = make_float2(re * S, I[c] * S);
        }
        float4* dst = (float4*)(g_A + (((size_t)(b * EM1 + kw)) * HH + h) * CC + ci0);
        dst[0] = make_float4(o[0].x, o[0].y, o[1].x, o[1].y);
        dst[1] = make_float4(o[2].x, o[2].y, o[3].x, o[3].y);
    }
    // kw = 0 epilogue: real sum over all w
    {
        int c = tid & 31, grp = tid >> 5;
        float acc = 0.f;
#pragma unroll 8
        for (int w = grp * 32; w < grp * 32 + 32; w++) acc += sU[w][c];
        sRed[grp][c] = acc;
        __syncthreads();
        if (tid < 32) {
            float r = (sRed[0][tid] + sRed[1][tid] + sRed[2][tid] + sRed[3][tid]
                       + sV[0][tid]) * S;
            g_A[(((size_t)(b * EM1 + 0)) * HH + h) * CC + tid] = make_float2(r, 0.f);
        }
    }
}

// ---------------- K2: H-DFT (folded, 17 freqs -> 32 outputs) ----------------
__global__ void __launch_bounds__(128) k2_hdft() {
    __shared__ __align__(16) float2 sU[128 * 16];   // [h][cil]  (h=0: a0; sV h=0: a128)
    __shared__ __align__(16) float2 sV[128 * 16];
    __shared__ float2 sT[256];
    __shared__ float2 sRedC[8][16];
    int blk = blockIdx.x;
    int half = blk & 1; int bk = blk >> 1;
    int b = bk / EM1, kw = bk % EM1;
    int tid = threadIdx.x;
    const float2* A = g_A + ((size_t)(b * EM1 + kw)) * (HH * CC) + half * 16;
    for (int i = tid; i < 256; i += 128) sT[i] = g_tw[i];
    for (int i = tid; i < 2048; i += 128) {
        int h = i >> 4, c = i & 15;
        float2 a0 = A[h * CC + c];
        if (h == 0) {
            sU[c] = a0;                 // a[0]
            sV[c] = A[128 * CC + c];    // a[128]
        } else {
            float2 a1 = A[(256 - h) * CC + c];
            sU[i] = make_float2(a0.x + a1.x, a0.y + a1.y);
            sV[i] = make_float2(a0.x - a1.x, a0.y - a1.y);
        }
    }
    __syncthreads();
    int cig = tid & 7, fg = tid >> 3;
    int c0 = cig * 2;
    int f = fg + 1;                      // 1..16
    float Cr0 = 0, Ci0 = 0, Cr1 = 0, Ci1 = 0;
    float Sr0 = 0, Si0 = 0, Sr1 = 0, Si1 = 0;
    int ti = f;
#pragma unroll 4
    for (int h = 1; h < 128; h++) {
        float2 t = sT[ti];
        ti = (ti + f) & 255;
        float4 u = *(const float4*)&sU[h * 16 + c0];
        float4 v = *(const float4*)&sV[h * 16 + c0];
        Cr0 += u.x * t.x; Ci0 += u.y * t.x; Cr1 += u.z * t.x; Ci1 += u.w * t.x;
        Sr0 += v.x * t.y; Si0 += v.y * t.y; Sr1 += v.z * t.y; Si1 += v.w * t.y;
    }
    {
        float sgn = (f & 1) ? -1.0f : 1.0f;
        float2 a0a = sU[c0], a0b = sU[c0 + 1];
        float2 a1a = sV[c0], a1b = sV[c0 + 1];
        Cr0 += a0a.x + sgn * a1a.x; Ci0 += a0a.y + sgn * a1a.y;
        Cr1 += a0b.x + sgn * a1b.x; Ci1 += a0b.y + sgn * a1b.y;
    }
    size_t obase = (size_t)kw * BB + b;
    if (f <= 15) {   // j = f : X = C - iS
        float4* dst = (float4*)(g_X + ((size_t)f * EM1 * BB + obase) * CC + half * 16 + c0);
        dst[0] = make_float4(Cr0 + Si0, Ci0 - Sr0, Cr1 + Si1, Ci1 - Sr1);
    }
    {                // j = 32 - f : X = C + iS
        int j = 32 - f;
        float4* dst = (float4*)(g_X + ((size_t)j * EM1 * BB + obase) * CC + half * 16 + c0);
        dst[0] = make_float4(Cr0 - Si0, Ci0 + Sr0, Cr1 - Si1, Ci1 + Sr1);
    }
    // f = 0 (j = 0): C0 = sum over all h
    {
        int cc = tid & 15, grp = tid >> 4;
        float2 acc = make_float2(0.f, 0.f);
#pragma unroll 4
        for (int h = grp * 16; h < grp * 16 + 16; h++) {
            float2 u = sU[h * 16 + cc];
            acc.x += u.x; acc.y += u.y;
        }
        sRedC[grp][cc] = acc;
        __syncthreads();
        if (tid < 16) {
            float2 s = make_float2(sV[tid].x, sV[tid].y);   // a128
#pragma unroll
            for (int g = 0; g < 8; g++) { s.x += sRedC[g][tid].x; s.y += sRedC[g][tid].y; }
            g_X[((size_t)0 * EM1 * BB + obase) * CC + half * 16 + tid] = s;
        }
    }
}

// ---------------- K3: per-mode 32x32 complex channel mixing ----------------
__global__ void __launch_bounds__(128) k3_mix() {
    __shared__ float2 sW[1024];
    __shared__ float2 sX[512];
    int j = blockIdx.x / EM1, kw = blockIdx.x % EM1;
    int tid = threadIdx.x;
    const float4* wsrc = (const float4*)(g_Wt + ((size_t)(j * EM1 + kw)) * 1024);
    float4* sW4 = (float4*)sW;
    for (int i = tid; i < 512; i += 128) sW4[i] = wsrc[i];
    const float4* xsrc = (const float4*)(g_X + ((size_t)(j * EM1 + kw)) * BB * CC);
    float4* sX4 = (float4*)sX;
    for (int i = tid; i < 256; i += 128) sX4[i] = xsrc[i];
    __syncthreads();
    int co = tid & 31, bg = tid >> 5;
    float yR[4] = {0,0,0,0}, yI[4] = {0,0,0,0};
#pragma unroll 8
    for (int ci = 0; ci < 32; ci++) {
        float2 wv = sW[ci * 32 + co];
#pragma unroll
        for (int s = 0; s < 4; s++) {
            float2 xv = sX[(bg * 4 + s) * 32 + ci];
            yR[s] += xv.x * wv.x - xv.y * wv.y;
            yI[s] += xv.x * wv.y + xv.y * wv.x;
        }
    }
#pragma unroll
    for (int s = 0; s < 4; s++) {
        int b = bg * 4 + s;
        g_Y[(((size_t)(b * EM1 + kw)) * NROW + j) * CC + co] = make_float2(yR[s], yI[s]);
    }
}

// ---------------- K4: H-inverse (folded: 17 P/Q freqs -> 256 h) ----------------
__global__ void __launch_bounds__(128) k4_hinv() {
    __shared__ __align__(16) float2 sP[EM1 * 32];
    __shared__ __align__(16) float2 sQ[EM1 * 32];
    __shared__ float2 sT[256];
    int blk = blockIdx.x;
    int half = blk & 1; int bk = blk >> 1;
    int b = bk / EM1, kw = bk % EM1;
    int tid = threadIdx.x;
    const float2* Y = g_Y + ((size_t)(b * EM1 + kw)) * (NROW * CC);
    for (int i = tid; i < 256; i += 128) sT[i] = g_tw[i];
    for (int i = tid; i < EM1 * 32; i += 128) {
        int f = i >> 5, c = i & 31;
        float2 p, q;
        if (f == 0) { p = Y[c]; q = make_float2(0.f, 0.f); }
        else if (f == 16) { float2 yb = Y[16 * CC + c]; p = yb; q = make_float2(-yb.x, -yb.y); }
        else {
            float2 ya = Y[f * CC + c], yb = Y[(32 - f) * CC + c];
            p = make_float2(ya.x + yb.x, ya.y + yb.y);
            q = make_float2(ya.x - yb.x, ya.y - yb.y);
        }
        sP[i] = p; sQ[i] = q;
    }
    __syncthreads();
    int cig = tid & 7, hg = tid >> 3;
    int c0 = cig * 4;
    float Er[4][4], Ei[4][4], Or_[4][4], Oi[4][4];
#pragma unroll
    for (int m = 0; m < 4; m++)
#pragma unroll
        for (int c = 0; c < 4; c++) { Er[m][c]=0; Ei[m][c]=0; Or_[m][c]=0; Oi[m][c]=0; }
    int hbase = half * 64 + hg;
#pragma unroll
    for (int f = 0; f < 17; f++) {
        float4 p01 = *(const float4*)&sP[f * 32 + c0];
        float4 p23 = *(const float4*)&sP[f * 32 + c0 + 2];
        float4 q01 = *(const float4*)&sQ[f * 32 + c0];
        float4 q23 = *(const float4*)&sQ[f * 32 + c0 + 2];
#pragma unroll
        for (int m = 0; m < 4; m++) {
            int h = hbase + 16 * m;
            float2 t = sT[(f * h) & 255];
            Er[m][0] += p01.x * t.x; Ei[m][0] += p01.y * t.x;
            Or_[m][0] += q01.x * t.y; Oi[m][0] += q01.y * t.y;
            Er[m][1] += p01.z * t.x; Ei[m][1] += p01.w * t.x;
            Or_[m][1] += q01.z * t.y; Oi[m][1] += q01.w * t.y;
            Er[m][2] += p23.x * t.x; Ei[m][2] += p23.y * t.x;
            Or_[m][2] += q23.x * t.y; Oi[m][2] += q23.y * t.y;
            Er[m][3] += p23.z * t.x; Ei[m][3] += p23.w * t.x;
            Or_[m][3] += q23.z * t.y; Oi[m][3] += q23.w * t.y;
        }
    }
#pragma unroll
    for (int m = 0; m < 4; m++) {
        int h = hbase + 16 * m;
        int row = b * 256 + h;
        float4* d0 = (float4*)(g_Z + ((size_t)row * EM1 + kw) * CC + c0);
        d0[0] = make_float4(Er[m][0] - Oi[m][0], Ei[m][0] + Or_[m][0],
                            Er[m][1] - Oi[m][1], Ei[m][1] + Or_[m][1]);
        d0[1] = make_float4(Er[m][2] - Oi[m][2], Ei[m][2] + Or_[m][2],
                            Er[m][3] - Oi[m][3], Ei[m][3] + Or_[m][3]);
        if (h != 0) {
            int row2 = b * 256 + (256 - h);
            float4* d1 = (float4*)(g_Z + ((size_t)row2 * EM1 + kw) * CC + c0);
            d1[0] = make_float4(Er[m][0] + Oi[m][0], Ei[m][0] - Or_[m][0],
                                Er[m][1] + Oi[m][1], Ei[m][1] - Or_[m][1]);
            d1[1] = make_float4(Er[m][2] + Oi[m][2], Ei[m][2] - Or_[m][2],
                                Er[m][3] + Oi[m][3], Ei[m][3] - Or_[m][3]);
        }
    }
    // h = 128: Z = sum_f (-1)^f P_f   (half==0 block only)
    if (half == 0 && tid < 32) {
        float2 acc = make_float2(0.f, 0.f);
#pragma unroll
        for (int f = 0; f < 17; f++) {
            float2 p = sP[f * 32 + tid];
            float s = (f & 1) ? -1.0f : 1.0f;
            acc.x += s * p.x; acc.y += s * p.y;
        }
        int row = b * 256 + 128;
        g_Z[((size_t)row * EM1 + kw) * CC + tid] = acc;
    }
}

// ---------------- K5: W-inverse (17 bins -> 256) + bias ----------------
__global__ void __launch_bounds__(128) k5_winv(const float* __restrict__ bias,
                                               float* __restrict__ out) {
    __shared__ __align__(16) float2 sZ[EM1 * 32];
    __shared__ float2 sT[256];
    __shared__ float sB[32];
    int row = blockIdx.x;
    int tid = threadIdx.x;
    const float4* src = (const float4*)(g_Z + (size_t)row * EM1 * CC);
    float4* sZ4 = (float4*)sZ;
    for (int i = tid; i < 272; i += 128) sZ4[i] = src[i];
    for (int i = tid; i < 256; i += 128) sT[i] = g_tw[i];
    if (tid < 32) sB[tid] = bias[tid];
    __syncthreads();
    int cig = tid & 7, wg = tid >> 3;
    int c0 = cig * 4;
    float base[4];
#pragma unroll
    for (int c = 0; c < 4; c++) base[c] = sZ[c0 + c].x + sB[c0 + c];
    float* orow = out + (size_t)row * 8192;
#pragma unroll
    for (int p = 0; p < 2; p++) {
        int w0 = wg + 16 * (4 * p);
        float P[4][4], Q[4][4];
        int idx[4];
#pragma unroll
        for (int q = 0; q < 4; q++) {
            idx[q] = (w0 + 16 * q) & 255;
#pragma unroll
            for (int c = 0; c < 4; c++) { P[q][c] = 0.f; Q[q][c] = 0.f; }
        }
#pragma unroll
        for (int k = 0; k < 16; k++) {
            float4 z01 = *(const float4*)&sZ[(k + 1) * 32 + c0];
            float4 z23 = *(const float4*)&sZ[(k + 1) * 32 + c0 + 2];
#pragma unroll
            for (int q = 0; q < 4; q++) {
                float2 t = sT[idx[q]];
                idx[q] = (idx[q] + w0 + 16 * q) & 255;
                P[q][0] += z01.x * t.x; Q[q][0] += z01.y * t.y;
                P[q][1] += z01.z * t.x; Q[q][1] += z01.w * t.y;
                P[q][2] += z23.x * t.x; Q[q][2] += z23.y * t.y;
                P[q][3] += z23.z * t.x; Q[q][3] += z23.w * t.y;
            }
        }
#pragma unroll
        for (int q = 0; q < 4; q++) {
            int w = w0 + 16 * q;
            *(float4*)(orow + w * 32 + c0) = make_float4(
                base[0] + 2.0f * (P[q][0] - Q[q][0]), base[1] + 2.0f * (P[q][1] - Q[q][1]),
                base[2] + 2.0f * (P[q][2] - Q[q][2]), base[3] + 2.0f * (P[q][3] - Q[q][3]));
            if (w != 0) {
                *(float4*)(orow + (256 - w) * 32 + c0) = make_float4(
                    base[0] + 2.0f * (P[q][0] + Q[q][0]), base[1] + 2.0f * (P[q][1] + Q[q][1]),
                    base[2] + 2.0f * (P[q][2] + Q[q][2]), base[3] + 2.0f * (P[q][3] + Q[q][3]));
            }
        }
    }
    // w = 128
    if (tid < 32) {
        float acc = 0.f;
#pragma unroll
        for (int k = 0; k < 16; k++) {
            float zr = sZ[(k + 1) * 32 + tid].x;
            acc += (k & 1) ? zr : -zr;
        }
        orow[128 * 32 + tid] = sZ[tid].x + sB[tid] + 2.0f * acc;
    }
}

extern "C" void kernel_launch(void* const* d_in, const int* in_sizes, int n_in,
                              void* d_out, int out_size) {
    const float* x    = (const float*)d_in[0];
    const float* w1r  = (const float*)d_in[1];
    const float* w1i  = (const float*)d_in[2];
    const float* w2r  = (const float*)d_in[3];
    const float* w2i  = (const float*)d_in[4];
    const float* bias = (const float*)d_in[5];
    float* out = (float*)d_out;

    k0_tw<<<1, 256>>>();
    kt_w<<<1088, 256>>>(w1r, w1i, w2r, w2i);
    k1_wdft<<<BB * HH, 128>>>(x);
    k2_hdft<<<BB * EM1 * 2, 128>>>();
    k3_mix<<<NROW * EM1, 128>>>();
    k4_hinv<<<BB * EM1 * 2, 128>>>();
    k5_winv<<<BB * HH, 128>>>(bias, out);
}

// round 5
// speedup vs baseline: 2.7690x; 1.4645x over previous
#include <cuda_runtime.h>
#include <math.h>

#define BB 16
#define HH 256
#define WW 256
#define CC 32
#define EM0 16
#define EM1 17
#define NROW 32

__device__ float2 g_tw[256];
__device__ float2 g_A[(size_t)BB * EM1 * HH * CC];    // A[b,kw][h][ci]
__device__ float2 g_X[(size_t)NROW * EM1 * BB * CC];  // X[j,kw][b][ci]
__device__ float2 g_Y[(size_t)BB * EM1 * NROW * CC];  // Y[b,kw][j][co]
__device__ float2 g_Z[(size_t)BB * HH * EM1 * CC];    // Z[row][kw][co]
__device__ float2 g_Wt[(size_t)NROW * EM1 * CC * CC]; // W[j,kw][ci][co]

// ---------------- K0: twiddles tw[k] = (cos,sin)(2*pi*k/256) ----------------
__global__ void k0_tw() {
    int t = threadIdx.x;
    float s, c;
    sincospif((float)t / 128.0f, &s, &c);
    g_tw[t] = make_float2(c, s);
}

// ---------------- Kt: weight transpose ----------------
__global__ void kt_w(const float* __restrict__ w1r, const float* __restrict__ w1i,
                     const float* __restrict__ w2r, const float* __restrict__ w2i) {
    int t = blockIdx.x * 256 + threadIdx.x;
    if (t >= CC * CC * EM0 * EM1) return;
    int kw = t % EM1; int r = t / EM1;
    int hh = r & 15;  r >>= 4;
    int co = r & 31;  int ci = r >> 5;
    g_Wt[((size_t)(hh * EM1 + kw)) * 1024 + ci * 32 + co] = make_float2(w1r[t], w1i[t]);
    g_Wt[((size_t)((hh + 16) * EM1 + kw)) * 1024 + ci * 32 + co] = make_float2(w2r[t], w2i[t]);
}

// ---------------- K1: W-DFT 256 -> 17 bins, double fold ----------------
// slot0: sUE=x0, sUO=x128, sVE=U64, sVO=V64
__global__ void __launch_bounds__(128) k1_wdft(const float* __restrict__ x) {
    __shared__ __align__(16) float sUE[64][32];
    __shared__ __align__(16) float sUO[64][32];
    __shared__ __align__(16) float sVE[64][32];
    __shared__ __align__(16) float sVO[64][32];
    __shared__ float2 sT[256];
    __shared__ float sRed[4][32];
    int row = blockIdx.x;
    int tid = threadIdx.x;
    for (int i = tid; i < 256; i += 128) sT[i] = g_tw[i];
    const float4* x4 = (const float4*)(x + (size_t)row * 8192);
    float4* UE4 = (float4*)sUE; float4* UO4 = (float4*)sUO;
    float4* VE4 = (float4*)sVE; float4* VO4 = (float4*)sVO;
#pragma unroll
    for (int it = 0; it < 4; it++) {
        int idx = tid + it * 128;
        int w = idx >> 3, cg = idx & 7;
        if (w == 0) {
            float4 a = x4[64 * 8 + cg];
            float4 b = x4[192 * 8 + cg];
            UE4[cg] = x4[cg];
            UO4[cg] = x4[128 * 8 + cg];
            VE4[cg] = make_float4(a.x + b.x, a.y + b.y, a.z + b.z, a.w + b.w);
            VO4[cg] = make_float4(a.x - b.x, a.y - b.y, a.z - b.z, a.w - b.w);
        } else {
            float4 a = x4[w * 8 + cg];
            float4 b = x4[(256 - w) * 8 + cg];
            float4 c = x4[(128 - w) * 8 + cg];
            float4 d = x4[(128 + w) * 8 + cg];
            UE4[w * 8 + cg] = make_float4(a.x + b.x + c.x + d.x, a.y + b.y + c.y + d.y,
                                          a.z + b.z + c.z + d.z, a.w + b.w + c.w + d.w);
            UO4[w * 8 + cg] = make_float4(a.x + b.x - c.x - d.x, a.y + b.y - c.y - d.y,
                                          a.z + b.z - c.z - d.z, a.w + b.w - c.w - d.w);
            VE4[w * 8 + cg] = make_float4(a.x - b.x + c.x - d.x, a.y - b.y + c.y - d.y,
                                          a.z - b.z + c.z - d.z, a.w - b.w + c.w - d.w);
            VO4[w * 8 + cg] = make_float4(a.x - b.x - c.x + d.x, a.y - b.y - c.y + d.y,
                                          a.z - b.z - c.z + d.z, a.w - b.w - c.w + d.w);
        }
    }
    __syncthreads();
    int lane = tid & 31, warp = tid >> 5;
    int cig = lane & 7, kwsub = lane >> 3;
    int k = warp * 4 + kwsub + 1;         // 1..16
    bool even = (k & 1) == 0;
    const float4* U = (even ? UE4 : UO4) + cig;
    const float4* V = (even ? VO4 : VE4) + cig;
    float R[4] = {0, 0, 0, 0}, I[4] = {0, 0, 0, 0};
    int tIdx = k;
#pragma unroll 7
    for (int w = 1; w < 64; w++) {
        float4 u = U[w * 8];
        float4 v = V[w * 8];
        float2 t = sT[tIdx];
        tIdx = (tIdx + k) & 255;
        R[0] += u.x * t.x; R[1] += u.y * t.x; R[2] += u.z * t.x; R[3] += u.w * t.x;
        I[0] -= v.x * t.y; I[1] -= v.y * t.y; I[2] -= v.z * t.y; I[3] -= v.w * t.y;
    }
    const float S = 1.0f / 65536.0f;
    int ci0 = cig * 4;
    int b = row >> 8, h = row & 255;
    {
        float sgn = ((k >> 1) & 1) ? -1.0f : 1.0f;
        float2 o[4];
#pragma unroll
        for (int c = 0; c < 4; c++) {
            float x0 = sUE[0][ci0 + c], x128 = sUO[0][ci0 + c];
            float u64 = sVE[0][ci0 + c], v64 = sVO[0][ci0 + c];
            float re, im;
            if (even) { re = R[c] + x0 + x128 + sgn * u64; im = I[c]; }
            else      { re = R[c] + x0 - x128;             im = I[c] - sgn * v64; }
            o[c] = make_float2(re * S, im * S);
        }
        float4* dst = (float4*)(g_A + (((size_t)(b * EM1 + k)) * HH + h) * CC + ci0);
        dst[0] = make_float4(o[0].x, o[0].y, o[1].x, o[1].y);
        dst[1] = make_float4(o[2].x, o[2].y, o[3].x, o[3].y);
    }
    // kw = 0: sum over all w = x0 + x128 + U64 + sum UE[1..63]
    {
        int c = tid & 31, grp = tid >> 5;
        float acc = 0.f;
#pragma unroll 4
        for (int w = grp * 16; w < grp * 16 + 16; w++) acc += sUE[w][c];
        sRed[grp][c] = acc;
        __syncthreads();
        if (tid < 32) {
            float r = (sRed[0][tid] + sRed[1][tid] + sRed[2][tid] + sRed[3][tid]
                       + sUO[0][tid] + sVE[0][tid]) * S;
            g_A[(((size_t)(b * EM1 + 0)) * HH + h) * CC + tid] = make_float2(r, 0.f);
        }
    }
}

// ---------------- K2: H-DFT (double-folded, 64 iters) ----------------
// slot0: sUE=a0, sUO=a128, sVE=U64, sVO=V64 (complex)
__global__ void __launch_bounds__(128) k2_hdft() {
    __shared__ __align__(16) float2 sUE[64 * 16];
    __shared__ __align__(16) float2 sUO[64 * 16];
    __shared__ __align__(16) float2 sVE[64 * 16];
    __shared__ __align__(16) float2 sVO[64 * 16];
    __shared__ float2 sT[256];
    __shared__ float2 sRedC[8][16];
    int blk = blockIdx.x;
    int half = blk & 1; int bk = blk >> 1;
    int b = bk / EM1, kw = bk % EM1;
    int tid = threadIdx.x;
    const float2* A = g_A + ((size_t)(b * EM1 + kw)) * (HH * CC) + half * 16;
    for (int i = tid; i < 256; i += 128) sT[i] = g_tw[i];
#pragma unroll
    for (int it = 0; it < 8; it++) {
        int i = tid + it * 128;
        int h = i >> 4, c = i & 15;
        if (h == 0) {
            float2 a64 = A[64 * CC + c], a192 = A[192 * CC + c];
            sUE[c] = A[c];
            sUO[c] = A[128 * CC + c];
            sVE[c] = make_float2(a64.x + a192.x, a64.y + a192.y);
            sVO[c] = make_float2(a64.x - a192.x, a64.y - a192.y);
        } else {
            float2 a = A[h * CC + c];
            float2 b2 = A[(256 - h) * CC + c];
            float2 cc = A[(128 - h) * CC + c];
            float2 d = A[(128 + h) * CC + c];
            sUE[i] = make_float2(a.x + b2.x + cc.x + d.x, a.y + b2.y + cc.y + d.y);
            sUO[i] = make_float2(a.x + b2.x - cc.x - d.x, a.y + b2.y - cc.y - d.y);
            sVE[i] = make_float2(a.x - b2.x + cc.x - d.x, a.y - b2.y + cc.y - d.y);
            sVO[i] = make_float2(a.x - b2.x - cc.x + d.x, a.y - b2.y - cc.y + d.y);
        }
    }
    __syncthreads();
    int cig = tid & 7, fg = tid >> 3;
    int c0 = cig * 2;
    int f = fg + 1;                      // 1..16
    bool even = (f & 1) == 0;
    const float2* Uc = (even ? sUE : sUO) + c0;
    const float2* Vs = (even ? sVO : sVE) + c0;
    float Cr0 = 0, Ci0 = 0, Cr1 = 0, Ci1 = 0;
    float Sr0 = 0, Si0 = 0, Sr1 = 0, Si1 = 0;
    int ti = f;
#pragma unroll 7
    for (int h = 1; h < 64; h++) {
        float2 t = sT[ti];
        ti = (ti + f) & 255;
        float4 u = *(const float4*)&Uc[h * 16];
        float4 v = *(const float4*)&Vs[h * 16];
        Cr0 += u.x * t.x; Ci0 += u.y * t.x; Cr1 += u.z * t.x; Ci1 += u.w * t.x;
        Sr0 += v.x * t.y; Si0 += v.y * t.y; Sr1 += v.z * t.y; Si1 += v.w * t.y;
    }
    {
        float sgn = ((f >> 1) & 1) ? -1.0f : 1.0f;
        float2 a0a = sUE[c0], a0b = sUE[c0 + 1];
        float2 a1a = sUO[c0], a1b = sUO[c0 + 1];
        if (even) {
            float2 u64a = sVE[c0], u64b = sVE[c0 + 1];
            Cr0 += a0a.x + a1a.x + sgn * u64a.x; Ci0 += a0a.y + a1a.y + sgn * u64a.y;
            Cr1 += a0b.x + a1b.x + sgn * u64b.x; Ci1 += a0b.y + a1b.y + sgn * u64b.y;
        } else {
            float2 v64a = sVO[c0], v64b = sVO[c0 + 1];
            Cr0 += a0a.x - a1a.x; Ci0 += a0a.y - a1a.y;
            Cr1 += a0b.x - a1b.x; Ci1 += a0b.y - a1b.y;
            Sr0 += sgn * v64a.x; Si0 += sgn * v64a.y;
            Sr1 += sgn * v64b.x; Si1 += sgn * v64b.y;
        }
    }
    size_t obase = (size_t)kw * BB + b;
    if (f <= 15) {   // j = f : X = C - iS
        float4* dst = (float4*)(g_X + ((size_t)f * EM1 * BB + obase) * CC + half * 16 + c0);
        dst[0] = make_float4(Cr0 + Si0, Ci0 - Sr0, Cr1 + Si1, Ci1 - Sr1);
    }
    {                // j = 32 - f : X = C + iS
        int j = 32 - f;
        float4* dst = (float4*)(g_X + ((size_t)j * EM1 * BB + obase) * CC + half * 16 + c0);
        dst[0] = make_float4(Cr0 - Si0, Ci0 + Sr0, Cr1 - Si1, Ci1 + Sr1);
    }
    // f = 0 (j = 0)
    {
        int cc = tid & 15, grp = tid >> 4;
        float2 acc = make_float2(0.f, 0.f);
#pragma unroll 4
        for (int h = grp * 8; h < grp * 8 + 8; h++) {
            float2 u = sUE[h * 16 + cc];
            acc.x += u.x; acc.y += u.y;
        }
        sRedC[grp][cc] = acc;
        __syncthreads();
        if (tid < 16) {
            float2 s = sUO[tid];                       // a128
            float2 u64 = sVE[tid];
            s.x += u64.x; s.y += u64.y;
#pragma unroll
            for (int g = 0; g < 8; g++) { s.x += sRedC[g][tid].x; s.y += sRedC[g][tid].y; }
            g_X[((size_t)0 * EM1 * BB + obase) * CC + half * 16 + tid] = s;
        }
    }
}

// ---------------- K3: per-mode 32x32 complex channel mixing ----------------
__global__ void __launch_bounds__(128) k3_mix() {
    __shared__ float2 sW[1024];
    __shared__ float2 sX[512];
    int j = blockIdx.x / EM1, kw = blockIdx.x % EM1;
    int tid = threadIdx.x;
    const float4* wsrc = (const float4*)(g_Wt + ((size_t)(j * EM1 + kw)) * 1024);
    float4* sW4 = (float4*)sW;
    for (int i = tid; i < 512; i += 128) sW4[i] = wsrc[i];
    const float4* xsrc = (const float4*)(g_X + ((size_t)(j * EM1 + kw)) * BB * CC);
    float4* sX4 = (float4*)sX;
    for (int i = tid; i < 256; i += 128) sX4[i] = xsrc[i];
    __syncthreads();
    int co = tid & 31, bg = tid >> 5;
    float yR[4] = {0,0,0,0}, yI[4] = {0,0,0,0};
#pragma unroll 8
    for (int ci = 0; ci < 32; ci++) {
        float2 wv = sW[ci * 32 + co];
#pragma unroll
        for (int s = 0; s < 4; s++) {
            float2 xv = sX[(bg * 4 + s) * 32 + ci];
            yR[s] += xv.x * wv.x - xv.y * wv.y;
            yI[s] += xv.x * wv.y + xv.y * wv.x;
        }
    }
#pragma unroll
    for (int s = 0; s < 4; s++) {
        int b = bg * 4 + s;
        g_Y[(((size_t)(b * EM1 + kw)) * NROW + j) * CC + co] = make_float2(yR[s], yI[s]);
    }
}

// ---------------- K4: H-inverse (parity fold: one pass -> 4 rows) ----------------
__global__ void __launch_bounds__(128) k4_hinv() {
    __shared__ __align__(16) float2 sP[EM1 * 16];
    __shared__ __align__(16) float2 sQ[EM1 * 16];
    __shared__ float2 sT[256];
    int blk = blockIdx.x;
    int half = blk & 1; int bk = blk >> 1;
    int b = bk / EM1, kw = bk % EM1;
    int tid = threadIdx.x;
    const float2* Y = g_Y + ((size_t)(b * EM1 + kw)) * (NROW * CC) + half * 16;
    for (int i = tid; i < 256; i += 128) sT[i] = g_tw[i];
    for (int i = tid; i < EM1 * 16; i += 128) {
        int f = i >> 4, c = i & 15;
        float2 p, q;
        if (f == 0) { p = Y[c]; q = make_float2(0.f, 0.f); }
        else if (f == 16) { float2 yb = Y[16 * CC + c]; p = yb; q = make_float2(-yb.x, -yb.y); }
        else {
            float2 ya = Y[f * CC + c], yb = Y[(32 - f) * CC + c];
            p = make_float2(ya.x + yb.x, ya.y + yb.y);
            q = make_float2(ya.x - yb.x, ya.y - yb.y);
        }
        sP[i] = p; sQ[i] = q;
    }
    __syncthreads();
    int cig = tid & 3, hg = tid >> 2;     // hg 0..31
    int c0 = cig * 4;                     // local ch (of 16)
    float EcR[2][4], EcI[2][4], OcR[2][4], OcI[2][4];
    float EsR[2][4], EsI[2][4], OsR[2][4], OsI[2][4];
    int hx[2];
#pragma unroll
    for (int m = 0; m < 2; m++) {
        hx[m] = 1 + hg + 32 * m;
#pragma unroll
        for (int c = 0; c < 4; c++) {
            EcR[m][c]=0; EcI[m][c]=0; OcR[m][c]=0; OcI[m][c]=0;
            EsR[m][c]=0; EsI[m][c]=0; OsR[m][c]=0; OsI[m][c]=0;
        }
    }
    int ti0 = 0, ti1 = 0;
#pragma unroll
    for (int f = 0; f < 17; f++) {
        float4 p01 = *(const float4*)&sP[f * 16 + c0];
        float4 p23 = *(const float4*)&sP[f * 16 + c0 + 2];
        float4 q01 = *(const float4*)&sQ[f * 16 + c0];
        float4 q23 = *(const float4*)&sQ[f * 16 + c0 + 2];
        float2 t0 = sT[ti0]; ti0 = (ti0 + hx[0]) & 255;
        float2 t1 = sT[ti1]; ti1 = (ti1 + hx[1]) & 255;
        if ((f & 1) == 0) {
            EcR[0][0] += p01.x*t0.x; EcI[0][0] += p01.y*t0.x; EsR[0][0] += q01.x*t0.y; EsI[0][0] += q01.y*t0.y;
            EcR[0][1] += p01.z*t0.x; EcI[0][1] += p01.w*t0.x; EsR[0][1] += q01.z*t0.y; EsI[0][1] += q01.w*t0.y;
            EcR[0][2] += p23.x*t0.x; EcI[0][2] += p23.y*t0.x; EsR[0][2] += q23.x*t0.y; EsI[0][2] += q23.y*t0.y;
            EcR[0][3] += p23.z*t0.x; EcI[0][3] += p23.w*t0.x; EsR[0][3] += q23.z*t0.y; EsI[0][3] += q23.w*t0.y;
            EcR[1][0] += p01.x*t1.x; EcI[1][0] += p01.y*t1.x; EsR[1][0] += q01.x*t1.y; EsI[1][0] += q01.y*t1.y;
            EcR[1][1] += p01.z*t1.x; EcI[1][1] += p01.w*t1.x; EsR[1][1] += q01.z*t1.y; EsI[1][1] += q01.w*t1.y;
            EcR[1][2] += p23.x*t1.x; EcI[1][2] += p23.y*t1.x; EsR[1][2] += q23.x*t1.y; EsI[1][2] += q23.y*t1.y;
            EcR[1][3] += p23.z*t1.x; EcI[1][3] += p23.w*t1.x; EsR[1][3] += q23.z*t1.y; EsI[1][3] += q23.w*t1.y;
        } else {
            OcR[0][0] += p01.x*t0.x; OcI[0][0] += p01.y*t0.x; OsR[0][0] += q01.x*t0.y; OsI[0][0] += q01.y*t0.y;
            OcR[0][1] += p01.z*t0.x; OcI[0][1] += p01.w*t0.x; OsR[0][1] += q01.z*t0.y; OsI[0][1] += q01.w*t0.y;
            OcR[0][2] += p23.x*t0.x; OcI[0][2] += p23.y*t0.x; OsR[0][2] += q23.x*t0.y; OsI[0][2] += q23.y*t0.y;
            OcR[0][3] += p23.z*t0.x; OcI[0][3] += p23.w*t0.x; OsR[0][3] += q23.z*t0.y; OsI[0][3] += q23.w*t0.y;
            OcR[1][0] += p01.x*t1.x; OcI[1][0] += p01.y*t1.x; OsR[1][0] += q01.x*t1.y; OsI[1][0] += q01.y*t1.y;
            OcR[1][1] += p01.z*t1.x; OcI[1][1] += p01.w*t1.x; OsR[1][1] += q01.z*t1.y; OsI[1][1] += q01.w*t1.y;
            OcR[1][2] += p23.x*t1.x; OcI[1][2] += p23.y*t1.x; OsR[1][2] += q23.x*t1.y; OsI[1][2] += q23.y*t1.y;
            OcR[1][3] += p23.z*t1.x; OcI[1][3] += p23.w*t1.x; OsR[1][3] += q23.z*t1.y; OsI[1][3] += q23.w*t1.y;
        }
    }
    int gc0 = half * 16 + c0;
#pragma unroll
    for (int m = 0; m < 2; m++) {
        int h = hx[m];
        float E1r[4], E1i[4], O1r[4], O1i[4], E2r[4], E2i[4], O2r[4], O2i[4];
#pragma unroll
        for (int c = 0; c < 4; c++) {
            E1r[c] = EcR[m][c] + OcR[m][c]; E1i[c] = EcI[m][c] + OcI[m][c];
            O1r[c] = EsR[m][c] + OsR[m][c]; O1i[c] = EsI[m][c] + OsI[m][c];
            E2r[c] = EcR[m][c] - OcR[m][c]; E2i[c] = EcI[m][c] - OcI[m][c];
            O2r[c] = -EsR[m][c] + OsR[m][c]; O2i[c] = -EsI[m][c] + OsI[m][c];
        }
        {
            int row = b * 256 + h;
            float4* d = (float4*)(g_Z + ((size_t)row * EM1 + kw) * CC + gc0);
            d[0] = make_float4(E1r[0]-O1i[0], E1i[0]+O1r[0], E1r[1]-O1i[1], E1i[1]+O1r[1]);
            d[1] = make_float4(E1r[2]-O1i[2], E1i[2]+O1r[2], E1r[3]-O1i[3], E1i[3]+O1r[3]);
            int row2 = b * 256 + (256 - h);
            float4* d2 = (float4*)(g_Z + ((size_t)row2 * EM1 + kw) * CC + gc0);
            d2[0] = make_float4(E1r[0]+O1i[0], E1i[0]-O1r[0], E1r[1]+O1i[1], E1i[1]-O1r[1]);
            d2[1] = make_float4(E1r[2]+O1i[2], E1i[2]-O1r[2], E1r[3]+O1i[3], E1i[3]-O1r[3]);
        }
        if (h != 64) {
            int row = b * 256 + (128 - h);
            float4* d = (float4*)(g_Z + ((size_t)row * EM1 + kw) * CC + gc0);
            d[0] = make_float4(E2r[0]-O2i[0], E2i[0]+O2r[0], E2r[1]-O2i[1], E2i[1]+O2r[1]);
            d[1] = make_float4(E2r[2]-O2i[2], E2i[2]+O2r[2], E2r[3]-O2i[3], E2i[3]+O2r[3]);
            int row2 = b * 256 + (128 + h);
            float4* d2 = (float4*)(g_Z + ((size_t)row2 * EM1 + kw) * CC + gc0);
            d2[0] = make_float4(E2r[0]+O2i[0], E2i[0]-O2r[0], E2r[1]+O2i[1], E2i[1]-O2r[1]);
            d2[1] = make_float4(E2r[2]+O2i[2], E2i[2]-O2r[2], E2r[3]+O2i[3], E2i[3]-O2r[3]);
        }
    }
    // h = 0 and h = 128
    if (tid < 32) {
        int c = tid & 15;
        bool is128 = tid >= 16;
        float2 acc = make_float2(0.f, 0.f);
#pragma unroll
        for (int f = 0; f < 17; f++) {
            float2 p = sP[f * 16 + c];
            float s = (is128 && (f & 1)) ? -1.0f : 1.0f;
            acc.x += s * p.x; acc.y += s * p.y;
        }
        int row = b * 256 + (is128 ? 128 : 0);
        g_Z[((size_t)row * EM1 + kw) * CC + half * 16 + c] = acc;
    }
}

// ---------------- K5: W-inverse (parity fold: one pass -> 4 cols) + bias ----------------
__global__ void __launch_bounds__(128) k5_winv(const float* __restrict__ bias,
                                               float* __restrict__ out) {
    __shared__ __align__(16) float2 sZ[EM1 * 32];
    __shared__ float2 sT[256];
    __shared__ float sB[32];
    int row = blockIdx.x;
    int tid = threadIdx.x;
    const float4* src = (const float4*)(g_Z + (size_t)row * EM1 * CC);
    float4* sZ4 = (float4*)sZ;
    for (int i = tid; i < 272; i += 128) sZ4[i] = src[i];
    for (int i = tid; i < 256; i += 128) sT[i] = g_tw[i];
    if (tid < 32) sB[tid] = bias[tid];
    __syncthreads();
    int cig = tid & 7, wg = tid >> 3;     // wg 0..15
    int c0 = cig * 4;
    float base[4];
#pragma unroll
    for (int c = 0; c < 4; c++) base[c] = sZ[c0 + c].x + sB[c0 + c];
    float* orow = out + (size_t)row * 8192;
    float Pe[4][4], Po[4][4], Qe[4][4], Qo[4][4];
    int wv[4], idx[4];
#pragma unroll
    for (int m = 0; m < 4; m++) {
        wv[m] = 1 + wg + 16 * m;          // 1..64
        idx[m] = wv[m];
#pragma unroll
        for (int c = 0; c < 4; c++) { Pe[m][c]=0; Po[m][c]=0; Qe[m][c]=0; Qo[m][c]=0; }
    }
#pragma unroll
    for (int k = 1; k <= 16; k++) {
        float4 z01 = *(const float4*)&sZ[k * 32 + c0];
        float4 z23 = *(const float4*)&sZ[k * 32 + c0 + 2];
#pragma unroll
        for (int m = 0; m < 4; m++) {
            float2 t = sT[idx[m]];
            idx[m] = (idx[m] + wv[m]) & 255;
            if ((k & 1) == 0) {
                Pe[m][0] += z01.x * t.x; Qe[m][0] += z01.y * t.y;
                Pe[m][1] += z01.z * t.x; Qe[m][1] += z01.w * t.y;
                Pe[m][2] += z23.x * t.x; Qe[m][2] += z23.y * t.y;
                Pe[m][3] += z23.z * t.x; Qe[m][3] += z23.w * t.y;
            } else {
                Po[m][0] += z01.x * t.x; Qo[m][0] += z01.y * t.y;
                Po[m][1] += z01.z * t.x; Qo[m][1] += z01.w * t.y;
                Po[m][2] += z23.x * t.x; Qo[m][2] += z23.y * t.y;
                Po[m][3] += z23.z * t.x; Qo[m][3] += z23.w * t.y;
            }
        }
    }
#pragma unroll
    for (int m = 0; m < 4; m++) {
        int w = wv[m];
        float4 o1, o2;
        o1 = make_float4(base[0] + 2.0f*(Pe[m][0]+Po[m][0]-Qe[m][0]-Qo[m][0]),
                         base[1] + 2.0f*(Pe[m][1]+Po[m][1]-Qe[m][1]-Qo[m][1]),
                         base[2] + 2.0f*(Pe[m][2]+Po[m][2]-Qe[m][2]-Qo[m][2]),
                         base[3] + 2.0f*(Pe[m][3]+Po[m][3]-Qe[m][3]-Qo[m][3]));
        o2 = make_float4(base[0] + 2.0f*(Pe[m][0]+Po[m][0]+Qe[m][0]+Qo[m][0]),
                         base[1] + 2.0f*(Pe[m][1]+Po[m][1]+Qe[m][1]+Qo[m][1]),
                         base[2] + 2.0f*(Pe[m][2]+Po[m][2]+Qe[m][2]+Qo[m][2]),
                         base[3] + 2.0f*(Pe[m][3]+Po[m][3]+Qe[m][3]+Qo[m][3]));
        *(float4*)(orow + w * 32 + c0) = o1;
        *(float4*)(orow + (256 - w) * 32 + c0) = o2;
        if (w != 64) {
            float4 o3, o4;
            o3 = make_float4(base[0] + 2.0f*(Pe[m][0]-Po[m][0]+Qe[m][0]-Qo[m][0]),
                             base[1] + 2.0f*(Pe[m][1]-Po[m][1]+Qe[m][1]-Qo[m][1]),
                             base[2] + 2.0f*(Pe[m][2]-Po[m][2]+Qe[m][2]-Qo[m][2]),
                             base[3] + 2.0f*(Pe[m][3]-Po[m][3]+Qe[m][3]-Qo[m][3]));
            o4 = make_float4(base[0] + 2.0f*(Pe[m][0]-Po[m][0]-Qe[m][0]+Qo[m][0]),
                             base[1] + 2.0f*(Pe[m][1]-Po[m][1]-Qe[m][1]+Qo[m][1]),
                             base[2] + 2.0f*(Pe[m][2]-Po[m][2]-Qe[m][2]+Qo[m][2]),
                             base[3] + 2.0f*(Pe[m][3]-Po[m][3]-Qe[m][3]+Qo[m][3]));
            *(float4*)(orow + (128 - w) * 32 + c0) = o3;
            *(float4*)(orow + (128 + w) * 32 + c0) = o4;
        }
    }
    // w = 0 and w = 128
    if (tid < 64) {
        int c = tid & 31;
        bool is128 = tid >= 32;
        float acc = 0.f;
#pragma unroll
        for (int k = 1; k <= 16; k++) {
            float zr = sZ[k * 32 + c].x;
            acc += (is128 && (k & 1)) ? -zr : zr;
        }
        orow[(is128 ? 128 * 32 : 0) + c] = sZ[c].x + sB[c] + 2.0f * acc;
    }
}

extern "C" void kernel_launch(void* const* d_in, const int* in_sizes, int n_in,
                              void* d_out, int out_size) {
    const float* x    = (const float*)d_in[0];
    const float* w1r  = (const float*)d_in[1];
    const float* w1i  = (const float*)d_in[2];
    const float* w2r  = (const float*)d_in[3];
    const float* w2i  = (const float*)d_in[4];
    const float* bias = (const float*)d_in[5];
    float* out = (float*)d_out;

    k0_tw<<<1, 256>>>();
    kt_w<<<1088, 256>>>(w1r, w1i, w2r, w2i);
    k1_wdft<<<BB * HH, 128>>>(x);
    k2_hdft<<<BB * EM1 * 2, 128>>>();
    k3_mix<<<NROW * EM1, 128>>>();
    k4_hinv<<<BB * EM1 * 2, 128>>>();
    k5_winv<<<BB * HH, 128>>>(bias, out);
}

// round 6
// speedup vs baseline: 2.9789x; 1.0758x over previous
#include <cuda_runtime.h>
#include <math.h>

#define BB 16
#define HH 256
#define WW 256
#define CC 32
#define EM0 16
#define EM1 17
#define NROW 32

__device__ float2 g_tw[256];
__device__ float2 g_A[(size_t)BB * EM1 * HH * CC];    // A[b,kw][h][ci]
__device__ float2 g_X[(size_t)NROW * EM1 * BB * CC];  // X[j,kw][b][ci]
__device__ float2 g_Y[(size_t)BB * EM1 * NROW * CC];  // Y[b,kw][j][co]
__device__ float2 g_Z[(size_t)BB * HH * EM1 * CC];    // Z[row][kw][co]
__device__ float2 g_Wt[(size_t)NROW * EM1 * CC * CC]; // W[j,kw][ci][co]

// ---------------- Kt: weight transpose (+ twiddle table in block 0) ----------------
__global__ void kt_w(const float* __restrict__ w1r, const float* __restrict__ w1i,
                     const float* __restrict__ w2r, const float* __restrict__ w2i) {
    if (blockIdx.x == 0) {
        int tt = threadIdx.x;
        float s, c;
        sincospif((float)tt / 128.0f, &s, &c);
        g_tw[tt] = make_float2(c, s);
    }
    int t = blockIdx.x * 256 + threadIdx.x;
    if (t >= CC * CC * EM0 * EM1) return;
    int kw = t % EM1; int r = t / EM1;
    int hh = r & 15;  r >>= 4;
    int co = r & 31;  int ci = r >> 5;
    float a1r = __ldcs(&w1r[t]), a1i = __ldcs(&w1i[t]);
    float a2r = __ldcs(&w2r[t]), a2i = __ldcs(&w2i[t]);
    g_Wt[((size_t)(hh * EM1 + kw)) * 1024 + ci * 32 + co] = make_float2(a1r, a1i);
    g_Wt[((size_t)((hh + 16) * EM1 + kw)) * 1024 + ci * 32 + co] = make_float2(a2r, a2i);
}

// ---------------- K1: W-DFT 256 -> 17 bins, double fold ----------------
// slot0: sUE=x0, sUO=x128, sVE=U64, sVO=V64
__global__ void __launch_bounds__(128) k1_wdft(const float* __restrict__ x) {
    __shared__ __align__(16) float sUE[64][32];
    __shared__ __align__(16) float sUO[64][32];
    __shared__ __align__(16) float sVE[64][32];
    __shared__ __align__(16) float sVO[64][32];
    __shared__ float2 sT[256];
    __shared__ float sRed[4][32];
    int row = blockIdx.x;
    int tid = threadIdx.x;
    for (int i = tid; i < 256; i += 128) sT[i] = g_tw[i];
    const float4* x4 = (const float4*)(x + (size_t)row * 8192);
    float4* UE4 = (float4*)sUE; float4* UO4 = (float4*)sUO;
    float4* VE4 = (float4*)sVE; float4* VO4 = (float4*)sVO;
#pragma unroll
    for (int it = 0; it < 4; it++) {
        int idx = tid + it * 128;
        int w = idx >> 3, cg = idx & 7;
        if (w == 0) {
            float4 a = __ldcs(&x4[64 * 8 + cg]);
            float4 b = __ldcs(&x4[192 * 8 + cg]);
            UE4[cg] = __ldcs(&x4[cg]);
            UO4[cg] = __ldcs(&x4[128 * 8 + cg]);
            VE4[cg] = make_float4(a.x + b.x, a.y + b.y, a.z + b.z, a.w + b.w);
            VO4[cg] = make_float4(a.x - b.x, a.y - b.y, a.z - b.z, a.w - b.w);
        } else {
            float4 a = __ldcs(&x4[w * 8 + cg]);
            float4 b = __ldcs(&x4[(256 - w) * 8 + cg]);
            float4 c = __ldcs(&x4[(128 - w) * 8 + cg]);
            float4 d = __ldcs(&x4[(128 + w) * 8 + cg]);
            UE4[w * 8 + cg] = make_float4(a.x + b.x + c.x + d.x, a.y + b.y + c.y + d.y,
                                          a.z + b.z + c.z + d.z, a.w + b.w + c.w + d.w);
            UO4[w * 8 + cg] = make_float4(a.x + b.x - c.x - d.x, a.y + b.y - c.y - d.y,
                                          a.z + b.z - c.z - d.z, a.w + b.w - c.w - d.w);
            VE4[w * 8 + cg] = make_float4(a.x - b.x + c.x - d.x, a.y - b.y + c.y - d.y,
                                          a.z - b.z + c.z - d.z, a.w - b.w + c.w - d.w);
            VO4[w * 8 + cg] = make_float4(a.x - b.x - c.x + d.x, a.y - b.y - c.y + d.y,
                                          a.z - b.z - c.z + d.z, a.w - b.w - c.w + d.w);
        }
    }
    __syncthreads();
    int lane = tid & 31, warp = tid >> 5;
    int cig = lane & 7, kwsub = lane >> 3;
    int k = warp * 4 + kwsub + 1;         // 1..16
    bool even = (k & 1) == 0;
    const float4* U = (even ? UE4 : UO4) + cig;
    const float4* V = (even ? VO4 : VE4) + cig;
    float R[4] = {0, 0, 0, 0}, I[4] = {0, 0, 0, 0};
    int tIdx = k;
#pragma unroll 7
    for (int w = 1; w < 64; w++) {
        float4 u = U[w * 8];
        float4 v = V[w * 8];
        float2 t = sT[tIdx];
        tIdx = (tIdx + k) & 255;
        R[0] += u.x * t.x; R[1] += u.y * t.x; R[2] += u.z * t.x; R[3] += u.w * t.x;
        I[0] -= v.x * t.y; I[1] -= v.y * t.y; I[2] -= v.z * t.y; I[3] -= v.w * t.y;
    }
    const float S = 1.0f / 65536.0f;
    int ci0 = cig * 4;
    int b = row >> 8, h = row & 255;
    {
        float sgn = ((k >> 1) & 1) ? -1.0f : 1.0f;
        float2 o[4];
#pragma unroll
        for (int c = 0; c < 4; c++) {
            float x0 = sUE[0][ci0 + c], x128 = sUO[0][ci0 + c];
            float u64 = sVE[0][ci0 + c], v64 = sVO[0][ci0 + c];
            float re, im;
            if (even) { re = R[c] + x0 + x128 + sgn * u64; im = I[c]; }
            else      { re = R[c] + x0 - x128;             im = I[c] - sgn * v64; }
            o[c] = make_float2(re * S, im * S);
        }
        float4* dst = (float4*)(g_A + (((size_t)(b * EM1 + k)) * HH + h) * CC + ci0);
        dst[0] = make_float4(o[0].x, o[0].y, o[1].x, o[1].y);
        dst[1] = make_float4(o[2].x, o[2].y, o[3].x, o[3].y);
    }
    // kw = 0: sum over all w = x0 + x128 + U64 + sum UE[1..63]
    {
        int c = tid & 31, grp = tid >> 5;
        float acc = 0.f;
#pragma unroll 4
        for (int w = grp * 16; w < grp * 16 + 16; w++) acc += sUE[w][c];
        sRed[grp][c] = acc;
        __syncthreads();
        if (tid < 32) {
            float r = (sRed[0][tid] + sRed[1][tid] + sRed[2][tid] + sRed[3][tid]
                       + sUO[0][tid] + sVE[0][tid]) * S;
            g_A[(((size_t)(b * EM1 + 0)) * HH + h) * CC + tid] = make_float2(r, 0.f);
        }
    }
}

// ---------------- K2: H-DFT (double-folded, 64 iters) ----------------
// slot0: sUE=a0, sUO=a128, sVE=U64, sVO=V64 (complex)
__global__ void __launch_bounds__(128) k2_hdft() {
    __shared__ __align__(16) float2 sUE[64 * 16];
    __shared__ __align__(16) float2 sUO[64 * 16];
    __shared__ __align__(16) float2 sVE[64 * 16];
    __shared__ __align__(16) float2 sVO[64 * 16];
    __shared__ float2 sT[256];
    __shared__ float2 sRedC[8][16];
    int blk = blockIdx.x;
    int half = blk & 1; int bk = blk >> 1;
    int b = bk / EM1, kw = bk % EM1;
    int tid = threadIdx.x;
    const float2* A = g_A + ((size_t)(b * EM1 + kw)) * (HH * CC) + half * 16;
    for (int i = tid; i < 256; i += 128) sT[i] = g_tw[i];
#pragma unroll
    for (int it = 0; it < 8; it++) {
        int i = tid + it * 128;
        int h = i >> 4, c = i & 15;
        if (h == 0) {
            float2 a64 = __ldcs(&A[64 * CC + c]), a192 = __ldcs(&A[192 * CC + c]);
            sUE[c] = __ldcs(&A[c]);
            sUO[c] = __ldcs(&A[128 * CC + c]);
            sVE[c] = make_float2(a64.x + a192.x, a64.y + a192.y);
            sVO[c] = make_float2(a64.x - a192.x, a64.y - a192.y);
        } else {
            float2 a = __ldcs(&A[h * CC + c]);
            float2 b2 = __ldcs(&A[(256 - h) * CC + c]);
            float2 cc = __ldcs(&A[(128 - h) * CC + c]);
            float2 d = __ldcs(&A[(128 + h) * CC + c]);
            sUE[i] = make_float2(a.x + b2.x + cc.x + d.x, a.y + b2.y + cc.y + d.y);
            sUO[i] = make_float2(a.x + b2.x - cc.x - d.x, a.y + b2.y - cc.y - d.y);
            sVE[i] = make_float2(a.x - b2.x + cc.x - d.x, a.y - b2.y + cc.y - d.y);
            sVO[i] = make_float2(a.x - b2.x - cc.x + d.x, a.y - b2.y - cc.y + d.y);
        }
    }
    __syncthreads();
    int cig = tid & 7, fg = tid >> 3;
    int c0 = cig * 2;
    int f = fg + 1;                      // 1..16
    bool even = (f & 1) == 0;
    const float2* Uc = (even ? sUE : sUO) + c0;
    const float2* Vs = (even ? sVO : sVE) + c0;
    float Cr0 = 0, Ci0 = 0, Cr1 = 0, Ci1 = 0;
    float Sr0 = 0, Si0 = 0, Sr1 = 0, Si1 = 0;
    int ti = f;
#pragma unroll 7
    for (int h = 1; h < 64; h++) {
        float2 t = sT[ti];
        ti = (ti + f) & 255;
        float4 u = *(const float4*)&Uc[h * 16];
        float4 v = *(const float4*)&Vs[h * 16];
        Cr0 += u.x * t.x; Ci0 += u.y * t.x; Cr1 += u.z * t.x; Ci1 += u.w * t.x;
        Sr0 += v.x * t.y; Si0 += v.y * t.y; Sr1 += v.z * t.y; Si1 += v.w * t.y;
    }
    {
        float sgn = ((f >> 1) & 1) ? -1.0f : 1.0f;
        float2 a0a = sUE[c0], a0b = sUE[c0 + 1];
        float2 a1a = sUO[c0], a1b = sUO[c0 + 1];
        if (even) {
            float2 u64a = sVE[c0], u64b = sVE[c0 + 1];
            Cr0 += a0a.x + a1a.x + sgn * u64a.x; Ci0 += a0a.y + a1a.y + sgn * u64a.y;
            Cr1 += a0b.x + a1b.x + sgn * u64b.x; Ci1 += a0b.y + a1b.y + sgn * u64b.y;
        } else {
            float2 v64a = sVO[c0], v64b = sVO[c0 + 1];
            Cr0 += a0a.x - a1a.x; Ci0 += a0a.y - a1a.y;
            Cr1 += a0b.x - a1b.x; Ci1 += a0b.y - a1b.y;
            Sr0 += sgn * v64a.x; Si0 += sgn * v64a.y;
            Sr1 += sgn * v64b.x; Si1 += sgn * v64b.y;
        }
    }
    size_t obase = (size_t)kw * BB + b;
    if (f <= 15) {   // j = f : X = C - iS
        float4* dst = (float4*)(g_X + ((size_t)f * EM1 * BB + obase) * CC + half * 16 + c0);
        dst[0] = make_float4(Cr0 + Si0, Ci0 - Sr0, Cr1 + Si1, Ci1 - Sr1);
    }
    {                // j = 32 - f : X = C + iS
        int j = 32 - f;
        float4* dst = (float4*)(g_X + ((size_t)j * EM1 * BB + obase) * CC + half * 16 + c0);
        dst[0] = make_float4(Cr0 - Si0, Ci0 + Sr0, Cr1 - Si1, Ci1 + Sr1);
    }
    // f = 0 (j = 0)
    {
        int cc = tid & 15, grp = tid >> 4;
        float2 acc = make_float2(0.f, 0.f);
#pragma unroll 4
        for (int h = grp * 8; h < grp * 8 + 8; h++) {
            float2 u = sUE[h * 16 + cc];
            acc.x += u.x; acc.y += u.y;
        }
        sRedC[grp][cc] = acc;
        __syncthreads();
        if (tid < 16) {
            float2 s = sUO[tid];                       // a128
            float2 u64 = sVE[tid];
            s.x += u64.x; s.y += u64.y;
#pragma unroll
            for (int g = 0; g < 8; g++) { s.x += sRedC[g][tid].x; s.y += sRedC[g][tid].y; }
            g_X[((size_t)0 * EM1 * BB + obase) * CC + half * 16 + tid] = s;
        }
    }
}

// ---------------- K3: per-mode 32x32 complex channel mixing ----------------
__global__ void __launch_bounds__(128) k3_mix() {
    __shared__ float2 sW[1024];
    __shared__ float2 sX[512];
    int j = blockIdx.x / EM1, kw = blockIdx.x % EM1;
    int tid = threadIdx.x;
    const float4* wsrc = (const float4*)(g_Wt + ((size_t)(j * EM1 + kw)) * 1024);
    float4* sW4 = (float4*)sW;
    for (int i = tid; i < 512; i += 128) sW4[i] = __ldcs(&wsrc[i]);
    const float4* xsrc = (const float4*)(g_X + ((size_t)(j * EM1 + kw)) * BB * CC);
    float4* sX4 = (float4*)sX;
    for (int i = tid; i < 256; i += 128) sX4[i] = __ldcs(&xsrc[i]);
    __syncthreads();
    int co = tid & 31, bg = tid >> 5;
    float yR[4] = {0,0,0,0}, yI[4] = {0,0,0,0};
#pragma unroll 8
    for (int ci = 0; ci < 32; ci++) {
        float2 wv = sW[ci * 32 + co];
#pragma unroll
        for (int s = 0; s < 4; s++) {
            float2 xv = sX[(bg * 4 + s) * 32 + ci];
            yR[s] += xv.x * wv.x - xv.y * wv.y;
            yI[s] += xv.x * wv.y + xv.y * wv.x;
        }
    }
#pragma unroll
    for (int s = 0; s < 4; s++) {
        int b = bg * 4 + s;
        g_Y[(((size_t)(b * EM1 + kw)) * NROW + j) * CC + co] = make_float2(yR[s], yI[s]);
    }
}

// ---------------- K4: H-inverse (parity fold: one pass -> 4 rows) ----------------
__global__ void __launch_bounds__(128) k4_hinv() {
    __shared__ __align__(16) float2 sP[EM1 * 16];
    __shared__ __align__(16) float2 sQ[EM1 * 16];
    __shared__ float2 sT[256];
    int blk = blockIdx.x;
    int half = blk & 1; int bk = blk >> 1;
    int b = bk / EM1, kw = bk % EM1;
    int tid = threadIdx.x;
    const float2* Y = g_Y + ((size_t)(b * EM1 + kw)) * (NROW * CC) + half * 16;
    for (int i = tid; i < 256; i += 128) sT[i] = g_tw[i];
    for (int i = tid; i < EM1 * 16; i += 128) {
        int f = i >> 4, c = i & 15;
        float2 p, q;
        if (f == 0) { p = __ldcs(&Y[c]); q = make_float2(0.f, 0.f); }
        else if (f == 16) {
            float2 yb = __ldcs(&Y[16 * CC + c]);
            p = yb; q = make_float2(-yb.x, -yb.y);
        } else {
            float2 ya = __ldcs(&Y[f * CC + c]), yb = __ldcs(&Y[(32 - f) * CC + c]);
            p = make_float2(ya.x + yb.x, ya.y + yb.y);
            q = make_float2(ya.x - yb.x, ya.y - yb.y);
        }
        sP[i] = p; sQ[i] = q;
    }
    __syncthreads();
    int cig = tid & 3, hg = tid >> 2;     // hg 0..31
    int c0 = cig * 4;                     // local ch (of 16)
    float EcR[2][4], EcI[2][4], OcR[2][4], OcI[2][4];
    float EsR[2][4], EsI[2][4], OsR[2][4], OsI[2][4];
    int hx[2];
#pragma unroll
    for (int m = 0; m < 2; m++) {
        hx[m] = 1 + hg + 32 * m;
#pragma unroll
        for (int c = 0; c < 4; c++) {
            EcR[m][c]=0; EcI[m][c]=0; OcR[m][c]=0; OcI[m][c]=0;
            EsR[m][c]=0; EsI[m][c]=0; OsR[m][c]=0; OsI[m][c]=0;
        }
    }
    int ti0 = 0, ti1 = 0;
#pragma unroll
    for (int f = 0; f < 17; f++) {
        float4 p01 = *(const float4*)&sP[f * 16 + c0];
        float4 p23 = *(const float4*)&sP[f * 16 + c0 + 2];
        float4 q01 = *(const float4*)&sQ[f * 16 + c0];
        float4 q23 = *(const float4*)&sQ[f * 16 + c0 + 2];
        float2 t0 = sT[ti0]; ti0 = (ti0 + hx[0]) & 255;
        float2 t1 = sT[ti1]; ti1 = (ti1 + hx[1]) & 255;
        if ((f & 1) == 0) {
            EcR[0][0] += p01.x*t0.x; EcI[0][0] += p01.y*t0.x; EsR[0][0] += q01.x*t0.y; EsI[0][0] += q01.y*t0.y;
            EcR[0][1] += p01.z*t0.x; EcI[0][1] += p01.w*t0.x; EsR[0][1] += q01.z*t0.y; EsI[0][1] += q01.w*t0.y;
            EcR[0][2] += p23.x*t0.x; EcI[0][2] += p23.y*t0.x; EsR[0][2] += q23.x*t0.y; EsI[0][2] += q23.y*t0.y;
            EcR[0][3] += p23.z*t0.x; EcI[0][3] += p23.w*t0.x; EsR[0][3] += q23.z*t0.y; EsI[0][3] += q23.w*t0.y;
            EcR[1][0] += p01.x*t1.x; EcI[1][0] += p01.y*t1.x; EsR[1][0] += q01.x*t1.y; EsI[1][0] += q01.y*t1.y;
            EcR[1][1] += p01.z*t1.x; EcI[1][1] += p01.w*t1.x; EsR[1][1] += q01.z*t1.y; EsI[1][1] += q01.w*t1.y;
            EcR[1][2] += p23.x*t1.x; EcI[1][2] += p23.y*t1.x; EsR[1][2] += q23.x*t1.y; EsI[1][2] += q23.y*t1.y;
            EcR[1][3] += p23.z*t1.x; EcI[1][3] += p23.w*t1.x; EsR[1][3] += q23.z*t1.y; EsI[1][3] += q23.w*t1.y;
        } else {
            OcR[0][0] += p01.x*t0.x; OcI[0][0] += p01.y*t0.x; OsR[0][0] += q01.x*t0.y; OsI[0][0] += q01.y*t0.y;
            OcR[0][1] += p01.z*t0.x; OcI[0][1] += p01.w*t0.x; OsR[0][1] += q01.z*t0.y; OsI[0][1] += q01.w*t0.y;
            OcR[0][2] += p23.x*t0.x; OcI[0][2] += p23.y*t0.x; OsR[0][2] += q23.x*t0.y; OsI[0][2] += q23.y*t0.y;
            OcR[0][3] += p23.z*t0.x; OcI[0][3] += p23.w*t0.x; OsR[0][3] += q23.z*t0.y; OsI[0][3] += q23.w*t0.y;
            OcR[1][0] += p01.x*t1.x; OcI[1][0] += p01.y*t1.x; OsR[1][0] += q01.x*t1.y; OsI[1][0] += q01.y*t1.y;
            OcR[1][1] += p01.z*t1.x; OcI[1][1] += p01.w*t1.x; OsR[1][1] += q01.z*t1.y; OsI[1][1] += q01.w*t1.y;
            OcR[1][2] += p23.x*t1.x; OcI[1][2] += p23.y*t1.x; OsR[1][2] += q23.x*t1.y; OsI[1][2] += q23.y*t1.y;
            OcR[1][3] += p23.z*t1.x; OcI[1][3] += p23.w*t1.x; OsR[1][3] += q23.z*t1.y; OsI[1][3] += q23.w*t1.y;
        }
    }
    int gc0 = half * 16 + c0;
#pragma unroll
    for (int m = 0; m < 2; m++) {
        int h = hx[m];
        float E1r[4], E1i[4], O1r[4], O1i[4], E2r[4], E2i[4], O2r[4], O2i[4];
#pragma unroll
        for (int c = 0; c < 4; c++) {
            E1r[c] = EcR[m][c] + OcR[m][c]; E1i[c] = EcI[m][c] + OcI[m][c];
            O1r[c] = EsR[m][c] + OsR[m][c]; O1i[c] = EsI[m][c] + OsI[m][c];
            E2r[c] = EcR[m][c] - OcR[m][c]; E2i[c] = EcI[m][c] - OcI[m][c];
            O2r[c] = -EsR[m][c] + OsR[m][c]; O2i[c] = -EsI[m][c] + OsI[m][c];
        }
        {
            int row = b * 256 + h;
            float4* d = (float4*)(g_Z + ((size_t)row * EM1 + kw) * CC + gc0);
            d[0] = make_float4(E1r[0]-O1i[0], E1i[0]+O1r[0], E1r[1]-O1i[1], E1i[1]+O1r[1]);
            d[1] = make_float4(E1r[2]-O1i[2], E1i[2]+O1r[2], E1r[3]-O1i[3], E1i[3]+O1r[3]);
            int row2 = b * 256 + (256 - h);
            float4* d2 = (float4*)(g_Z + ((size_t)row2 * EM1 + kw) * CC + gc0);
            d2[0] = make_float4(E1r[0]+O1i[0], E1i[0]-O1r[0], E1r[1]+O1i[1], E1i[1]-O1r[1]);
            d2[1] = make_float4(E1r[2]+O1i[2], E1i[2]-O1r[2], E1r[3]+O1i[3], E1i[3]-O1r[3]);
        }
        if (h != 64) {
            int row = b * 256 + (128 - h);
            float4* d = (float4*)(g_Z + ((size_t)row * EM1 + kw) * CC + gc0);
            d[0] = make_float4(E2r[0]-O2i[0], E2i[0]+O2r[0], E2r[1]-O2i[1], E2i[1]+O2r[1]);
            d[1] = make_float4(E2r[2]-O2i[2], E2i[2]+O2r[2], E2r[3]-O2i[3], E2i[3]+O2r[3]);
            int row2 = b * 256 + (128 + h);
            float4* d2 = (float4*)(g_Z + ((size_t)row2 * EM1 + kw) * CC + gc0);
            d2[0] = make_float4(E2r[0]+O2i[0], E2i[0]-O2r[0], E2r[1]+O2i[1], E2i[1]-O2r[1]);
            d2[1] = make_float4(E2r[2]+O2i[2], E2i[2]-O2r[2], E2r[3]+O2i[3], E2i[3]-O2r[3]);
        }
    }
    // h = 0 and h = 128
    if (tid < 32) {
        int c = tid & 15;
        bool is128 = tid >= 16;
        float2 acc = make_float2(0.f, 0.f);
#pragma unroll
        for (int f = 0; f < 17; f++) {
            float2 p = sP[f * 16 + c];
            float s = (is128 && (f & 1)) ? -1.0f : 1.0f;
            acc.x += s * p.x; acc.y += s * p.y;
        }
        int row = b * 256 + (is128 ? 128 : 0);
        g_Z[((size_t)row * EM1 + kw) * CC + half * 16 + c] = acc;
    }
}

// ---------------- K5: W-inverse (parity fold: one pass -> 4 cols) + bias ----------------
__global__ void __launch_bounds__(128) k5_winv(const float* __restrict__ bias,
                                               float* __restrict__ out) {
    __shared__ __align__(16) float2 sZ[EM1 * 32];
    __shared__ float2 sT[256];
    __shared__ float sB[32];
    int row = blockIdx.x;
    int tid = threadIdx.x;
    const float4* src = (const float4*)(g_Z + (size_t)row * EM1 * CC);
    float4* sZ4 = (float4*)sZ;
    for (int i = tid; i < 272; i += 128) sZ4[i] = __ldcs(&src[i]);
    for (int i = tid; i < 256; i += 128) sT[i] = g_tw[i];
    if (tid < 32) sB[tid] = bias[tid];
    __syncthreads();
    int cig = tid & 7, wg = tid >> 3;     // wg 0..15
    int c0 = cig * 4;
    float base[4];
#pragma unroll
    for (int c = 0; c < 4; c++) base[c] = sZ[c0 + c].x + sB[c0 + c];
    float* orow = out + (size_t)row * 8192;
    float Pe[4][4], Po[4][4], Qe[4][4], Qo[4][4];
    int wv[4], idx[4];
#pragma unroll
    for (int m = 0; m < 4; m++) {
        wv[m] = 1 + wg + 16 * m;          // 1..64
        idx[m] = wv[m];
#pragma unroll
        for (int c = 0; c < 4; c++) { Pe[m][c]=0; Po[m][c]=0; Qe[m][c]=0; Qo[m][c]=0; }
    }
#pragma unroll
    for (int k = 1; k <= 16; k++) {
        float4 z01 = *(const float4*)&sZ[k * 32 + c0];
        float4 z23 = *(const float4*)&sZ[k * 32 + c0 + 2];
#pragma unroll
        for (int m = 0; m < 4; m++) {
            float2 t = sT[idx[m]];
            idx[m] = (idx[m] + wv[m]) & 255;
            if ((k & 1) == 0) {
                Pe[m][0] += z01.x * t.x; Qe[m][0] += z01.y * t.y;
                Pe[m][1] += z01.z * t.x; Qe[m][1] += z01.w * t.y;
                Pe[m][2] += z23.x * t.x; Qe[m][2] += z23.y * t.y;
                Pe[m][3] += z23.z * t.x; Qe[m][3] += z23.w * t.y;
            } else {
                Po[m][0] += z01.x * t.x; Qo[m][0] += z01.y * t.y;
                Po[m][1] += z01.z * t.x; Qo[m][1] += z01.w * t.y;
                Po[m][2] += z23.x * t.x; Qo[m][2] += z23.y * t.y;
                Po[m][3] += z23.z * t.x; Qo[m][3] += z23.w * t.y;
            }
        }
    }
#pragma unroll
    for (int m = 0; m < 4; m++) {
        int w = wv[m];
        float4 o1, o2;
        o1 = make_float4(base[0] + 2.0f*(Pe[m][0]+Po[m][0]-Qe[m][0]-Qo[m][0]),
                         base[1] + 2.0f*(Pe[m][1]+Po[m][1]-Qe[m][1]-Qo[m][1]),
                         base[2] + 2.0f*(Pe[m][2]+Po[m][2]-Qe[m][2]-Qo[m][2]),
                         base[3] + 2.0f*(Pe[m][3]+Po[m][3]-Qe[m][3]-Qo[m][3]));
        o2 = make_float4(base[0] + 2.0f*(Pe[m][0]+Po[m][0]+Qe[m][0]+Qo[m][0]),
                         base[1] + 2.0f*(Pe[m][1]+Po[m][1]+Qe[m][1]+Qo[m][1]),
                         base[2] + 2.0f*(Pe[m][2]+Po[m][2]+Qe[m][2]+Qo[m][2]),
                         base[3] + 2.0f*(Pe[m][3]+Po[m][3]+Qe[m][3]+Qo[m][3]));
        __stcs((float4*)(orow + w * 32 + c0), o1);
        __stcs((float4*)(orow + (256 - w) * 32 + c0), o2);
        if (w != 64) {
            float4 o3, o4;
            o3 = make_float4(base[0] + 2.0f*(Pe[m][0]-Po[m][0]+Qe[m][0]-Qo[m][0]),
                             base[1] + 2.0f*(Pe[m][1]-Po[m][1]+Qe[m][1]-Qo[m][1]),
                             base[2] + 2.0f*(Pe[m][2]-Po[m][2]+Qe[m][2]-Qo[m][2]),
                             base[3] + 2.0f*(Pe[m][3]-Po[m][3]+Qe[m][3]-Qo[m][3]));
            o4 = make_float4(base[0] + 2.0f*(Pe[m][0]-Po[m][0]-Qe[m][0]+Qo[m][0]),
                             base[1] + 2.0f*(Pe[m][1]-Po[m][1]-Qe[m][1]+Qo[m][1]),
                             base[2] + 2.0f*(Pe[m][2]-Po[m][2]-Qe[m][2]+Qo[m][2]),
                             base[3] + 2.0f*(Pe[m][3]-Po[m][3]-Qe[m][3]+Qo[m][3]));
            __stcs((float4*)(orow + (128 - w) * 32 + c0), o3);
            __stcs((float4*)(orow + (128 + w) * 32 + c0), o4);
        }
    }
    // w = 0 and w = 128
    if (tid < 64) {
        int c = tid & 31;
        bool is128 = tid >= 32;
        float acc = 0.f;
#pragma unroll
        for (int k = 1; k <= 16; k++) {
            float zr = sZ[k * 32 + c].x;
            acc += (is128 && (k & 1)) ? -zr : zr;
        }
        __stcs(&orow[(is128 ? 128 * 32 : 0) + c], sZ[c].x + sB[c] + 2.0f * acc);
    }
}

extern "C" void kernel_launch(void* const* d_in, const int* in_sizes, int n_in,
                              void* d_out, int out_size) {
    const float* x    = (const float*)d_in[0];
    const float* w1r  = (const float*)d_in[1];
    const float* w1i  = (const float*)d_in[2];
    const float* w2r  = (const float*)d_in[3];
    const float* w2i  = (const float*)d_in[4];
    const float* bias = (const float*)d_in[5];
    float* out = (float*)d_out;

    kt_w<<<1088, 256>>>(w1r, w1i, w2r, w2i);
    k1_wdft<<<BB * HH, 128>>>(x);
    k2_hdft<<<BB * EM1 * 2, 128>>>();
    k3_mix<<<NROW * EM1, 128>>>();
    k4_hinv<<<BB * EM1 * 2, 128>>>();
    k5_winv<<<BB * HH, 128>>>(bias, out);
}

// round 9
// speedup vs baseline: 3.0464x; 1.0227x over previous
#include <cuda_runtime.h>
#include <math.h>

#define BB 16
#define HH 256
#define WW 256
#define CC 32
#define EM0 16
#define EM1 17
#define NROW 32

__device__ float2 g_tw[256];
__device__ float2 g_A[(size_t)BB * EM1 * HH * CC];    // A[b,kw][h][ci]
__device__ float2 g_X[(size_t)NROW * EM1 * BB * CC];  // X[j,kw][b][ci]
__device__ float2 g_Z[(size_t)BB * HH * EM1 * CC];    // Z[row][kw][co]
__device__ float2 g_Wt[(size_t)NROW * EM1 * CC * CC]; // W[j,kw][ci][co]

// ---------------- Kt: weight transpose (+ twiddle table in block 0) ----------------
__global__ void kt_w(const float* __restrict__ w1r, const float* __restrict__ w1i,
                     const float* __restrict__ w2r, const float* __restrict__ w2i) {
    if (blockIdx.x == 0) {
        int tt = threadIdx.x;
        float s, c;
        sincospif((float)tt / 128.0f, &s, &c);
        g_tw[tt] = make_float2(c, s);
    }
    int t = blockIdx.x * 256 + threadIdx.x;
    if (t >= CC * CC * EM0 * EM1) return;
    int kw = t % EM1; int r = t / EM1;
    int hh = r & 15;  r >>= 4;
    int co = r & 31;  int ci = r >> 5;
    float a1r = __ldcs(&w1r[t]), a1i = __ldcs(&w1i[t]);
    float a2r = __ldcs(&w2r[t]), a2i = __ldcs(&w2i[t]);
    g_Wt[((size_t)(hh * EM1 + kw)) * 1024 + ci * 32 + co] = make_float2(a1r, a1i);
    g_Wt[((size_t)((hh + 16) * EM1 + kw)) * 1024 + ci * 32 + co] = make_float2(a2r, a2i);
}

// ---------------- K1: W-DFT 256 -> 17 bins, double fold ----------------
__global__ void __launch_bounds__(128) k1_wdft(const float* __restrict__ x) {
    __shared__ __align__(16) float sUE[64][32];
    __shared__ __align__(16) float sUO[64][32];
    __shared__ __align__(16) float sVE[64][32];
    __shared__ __align__(16) float sVO[64][32];
    __shared__ float2 sT[256];
    __shared__ float sRed[4][32];
    int row = blockIdx.x;
    int tid = threadIdx.x;
    for (int i = tid; i < 256; i += 128) sT[i] = g_tw[i];
    const float4* x4 = (const float4*)(x + (size_t)row * 8192);
    float4* UE4 = (float4*)sUE; float4* UO4 = (float4*)sUO;
    float4* VE4 = (float4*)sVE; float4* VO4 = (float4*)sVO;
#pragma unroll
    for (int it = 0; it < 4; it++) {
        int idx = tid + it * 128;
        int w = idx >> 3, cg = idx & 7;
        if (w == 0) {
            float4 a = __ldcs(&x4[64 * 8 + cg]);
            float4 b = __ldcs(&x4[192 * 8 + cg]);
            UE4[cg] = __ldcs(&x4[cg]);
            UO4[cg] = __ldcs(&x4[128 * 8 + cg]);
            VE4[cg] = make_float4(a.x + b.x, a.y + b.y, a.z + b.z, a.w + b.w);
            VO4[cg] = make_float4(a.x - b.x, a.y - b.y, a.z - b.z, a.w - b.w);
        } else {
            float4 a = __ldcs(&x4[w * 8 + cg]);
            float4 b = __ldcs(&x4[(256 - w) * 8 + cg]);
            float4 c = __ldcs(&x4[(128 - w) * 8 + cg]);
            float4 d = __ldcs(&x4[(128 + w) * 8 + cg]);
            UE4[w * 8 + cg] = make_float4(a.x + b.x + c.x + d.x, a.y + b.y + c.y + d.y,
                                          a.z + b.z + c.z + d.z, a.w + b.w + c.w + d.w);
            UO4[w * 8 + cg] = make_float4(a.x + b.x - c.x - d.x, a.y + b.y - c.y - d.y,
                                          a.z + b.z - c.z - d.z, a.w + b.w - c.w - d.w);
            VE4[w * 8 + cg] = make_float4(a.x - b.x + c.x - d.x, a.y - b.y + c.y - d.y,
                                          a.z - b.z + c.z - d.z, a.w - b.w + c.w - d.w);
            VO4[w * 8 + cg] = make_float4(a.x - b.x - c.x + d.x, a.y - b.y - c.y + d.y,
                                          a.z - b.z - c.z + d.z, a.w - b.w - c.w + d.w);
        }
    }
    __syncthreads();
    int lane = tid & 31, warp = tid >> 5;
    int cig = lane & 7, kwsub = lane >> 3;
    int k = warp * 4 + kwsub + 1;         // 1..16
    bool even = (k & 1) == 0;
    const float4* U = (even ? UE4 : UO4) + cig;
    const float4* V = (even ? VO4 : VE4) + cig;
    float R[4] = {0, 0, 0, 0}, I[4] = {0, 0, 0, 0};
    int tIdx = k;
#pragma unroll 7
    for (int w = 1; w < 64; w++) {
        float4 u = U[w * 8];
        float4 v = V[w * 8];
        float2 t = sT[tIdx];
        tIdx = (tIdx + k) & 255;
        R[0] += u.x * t.x; R[1] += u.y * t.x; R[2] += u.z * t.x; R[3] += u.w * t.x;
        I[0] -= v.x * t.y; I[1] -= v.y * t.y; I[2] -= v.z * t.y; I[3] -= v.w * t.y;
    }
    const float S = 1.0f / 65536.0f;
    int ci0 = cig * 4;
    int b = row >> 8, h = row & 255;
    {
        float sgn = ((k >> 1) & 1) ? -1.0f : 1.0f;
        float2 o[4];
#pragma unroll
        for (int c = 0; c < 4; c++) {
            float x0 = sUE[0][ci0 + c], x128 = sUO[0][ci0 + c];
            float u64 = sVE[0][ci0 + c], v64 = sVO[0][ci0 + c];
            float re, im;
            if (even) { re = R[c] + x0 + x128 + sgn * u64; im = I[c]; }
            else      { re = R[c] + x0 - x128;             im = I[c] - sgn * v64; }
            o[c] = make_float2(re * S, im * S);
        }
        float4* dst = (float4*)(g_A + (((size_t)(b * EM1 + k)) * HH + h) * CC + ci0);
        dst[0] = make_float4(o[0].x, o[0].y, o[1].x, o[1].y);
        dst[1] = make_float4(o[2].x, o[2].y, o[3].x, o[3].y);
    }
    // kw = 0
    {
        int c = tid & 31, grp = tid >> 5;
        float acc = 0.f;
#pragma unroll 4
        for (int w = grp * 16; w < grp * 16 + 16; w++) acc += sUE[w][c];
        sRed[grp][c] = acc;
        __syncthreads();
        if (tid < 32) {
            float r = (sRed[0][tid] + sRed[1][tid] + sRed[2][tid] + sRed[3][tid]
                       + sUO[0][tid] + sVE[0][tid]) * S;
            g_A[(((size_t)(b * EM1 + 0)) * HH + h) * CC + tid] = make_float2(r, 0.f);
        }
    }
}

// ---------------- K2: H-DFT (double-folded, 64 iters) ----------------
__global__ void __launch_bounds__(128) k2_hdft() {
    __shared__ __align__(16) float2 sUE[64 * 16];
    __shared__ __align__(16) float2 sUO[64 * 16];
    __shared__ __align__(16) float2 sVE[64 * 16];
    __shared__ __align__(16) float2 sVO[64 * 16];
    __shared__ float2 sT[256];
    __shared__ float2 sRedC[8][16];
    int blk = blockIdx.x;
    int half = blk & 1; int bk = blk >> 1;
    int b = bk / EM1, kw = bk % EM1;
    int tid = threadIdx.x;
    const float2* A = g_A + ((size_t)(b * EM1 + kw)) * (HH * CC) + half * 16;
    for (int i = tid; i < 256; i += 128) sT[i] = g_tw[i];
#pragma unroll
    for (int it = 0; it < 8; it++) {
        int i = tid + it * 128;
        int h = i >> 4, c = i & 15;
        if (h == 0) {
            float2 a64 = __ldcs(&A[64 * CC + c]), a192 = __ldcs(&A[192 * CC + c]);
            sUE[c] = __ldcs(&A[c]);
            sUO[c] = __ldcs(&A[128 * CC + c]);
            sVE[c] = make_float2(a64.x + a192.x, a64.y + a192.y);
            sVO[c] = make_float2(a64.x - a192.x, a64.y - a192.y);
        } else {
            float2 a = __ldcs(&A[h * CC + c]);
            float2 b2 = __ldcs(&A[(256 - h) * CC + c]);
            float2 cc = __ldcs(&A[(128 - h) * CC + c]);
            float2 d = __ldcs(&A[(128 + h) * CC + c]);
            sUE[i] = make_float2(a.x + b2.x + cc.x + d.x, a.y + b2.y + cc.y + d.y);
            sUO[i] = make_float2(a.x + b2.x - cc.x - d.x, a.y + b2.y - cc.y - d.y);
            sVE[i] = make_float2(a.x - b2.x + cc.x - d.x, a.y - b2.y + cc.y - d.y);
            sVO[i] = make_float2(a.x - b2.x - cc.x + d.x, a.y - b2.y - cc.y + d.y);
        }
    }
    __syncthreads();
    int cig = tid & 7, fg = tid >> 3;
    int c0 = cig * 2;
    int f = fg + 1;                      // 1..16
    bool even = (f & 1) == 0;
    const float2* Uc = (even ? sUE : sUO) + c0;
    const float2* Vs = (even ? sVO : sVE) + c0;
    float Cr0 = 0, Ci0 = 0, Cr1 = 0, Ci1 = 0;
    float Sr0 = 0, Si0 = 0, Sr1 = 0, Si1 = 0;
    int ti = f;
#pragma unroll 7
    for (int h = 1; h < 64; h++) {
        float2 t = sT[ti];
        ti = (ti + f) & 255;
        float4 u = *(const float4*)&Uc[h * 16];
        float4 v = *(const float4*)&Vs[h * 16];
        Cr0 += u.x * t.x; Ci0 += u.y * t.x; Cr1 += u.z * t.x; Ci1 += u.w * t.x;
        Sr0 += v.x * t.y; Si0 += v.y * t.y; Sr1 += v.z * t.y; Si1 += v.w * t.y;
    }
    {
        float sgn = ((f >> 1) & 1) ? -1.0f : 1.0f;
        float2 a0a = sUE[c0], a0b = sUE[c0 + 1];
        float2 a1a = sUO[c0], a1b = sUO[c0 + 1];
        if (even) {
            float2 u64a = sVE[c0], u64b = sVE[c0 + 1];
            Cr0 += a0a.x + a1a.x + sgn * u64a.x; Ci0 += a0a.y + a1a.y + sgn * u64a.y;
            Cr1 += a0b.x + a1b.x + sgn * u64b.x; Ci1 += a0b.y + a1b.y + sgn * u64b.y;
        } else {
            float2 v64a = sVO[c0], v64b = sVO[c0 + 1];
            Cr0 += a0a.x - a1a.x; Ci0 += a0a.y - a1a.y;
            Cr1 += a0b.x - a1b.x; Ci1 += a0b.y - a1b.y;
            Sr0 += sgn * v64a.x; Si0 += sgn * v64a.y;
            Sr1 += sgn * v64b.x; Si1 += sgn * v64b.y;
        }
    }
    size_t obase = (size_t)kw * BB + b;
    if (f <= 15) {   // j = f : X = C - iS
        float4* dst = (float4*)(g_X + ((size_t)f * EM1 * BB + obase) * CC + half * 16 + c0);
        dst[0] = make_float4(Cr0 + Si0, Ci0 - Sr0, Cr1 + Si1, Ci1 - Sr1);
    }
    {                // j = 32 - f : X = C + iS
        int j = 32 - f;
        float4* dst = (float4*)(g_X + ((size_t)j * EM1 * BB + obase) * CC + half * 16 + c0);
        dst[0] = make_float4(Cr0 - Si0, Ci0 + Sr0, Cr1 - Si1, Ci1 + Sr1);
    }
    // f = 0 (j = 0)
    {
        int cc = tid & 15, grp = tid >> 4;
        float2 acc = make_float2(0.f, 0.f);
#pragma unroll 4
        for (int h = grp * 8; h < grp * 8 + 8; h++) {
            float2 u = sUE[h * 16 + cc];
            acc.x += u.x; acc.y += u.y;
        }
        sRedC[grp][cc] = acc;
        __syncthreads();
        if (tid < 16) {
            float2 s = sUO[tid];                       // a128
            float2 u64 = sVE[tid];
            s.x += u64.x; s.y += u64.y;
#pragma unroll
            for (int g = 0; g < 8; g++) { s.x += sRedC[g][tid].x; s.y += sRedC[g][tid].y; }
            g_X[((size_t)0 * EM1 * BB + obase) * CC + half * 16 + tid] = s;
        }
    }
}

// ---------------- K34: channel mix + H-inverse fused ----------------
// block = (b, kw, co-half). Loads X[j][ci] (all 32 j x 32 ci), streams the
// weight half-tile, mixes into sY[j][16 co], then folded H-inverse -> g_Z.
__global__ void __launch_bounds__(128) k34_mixhinv() {
    __shared__ __align__(16) float2 sX[NROW * CC];    // [j][ci] 8KB
    __shared__ __align__(16) float2 sY[NROW * 16];    // [j][col] 4KB
    __shared__ __align__(16) float2 sP[EM1 * 16];
    __shared__ __align__(16) float2 sQ[EM1 * 16];
    __shared__ float2 sT[256];
    int blk = blockIdx.x;
    int half = blk & 1; int bk = blk >> 1;
    int b = bk / EM1, kw = bk % EM1;
    int tid = threadIdx.x;
    for (int i = tid; i < 256; i += 128) sT[i] = g_tw[i];
    // load X[j][ci]: per j a contiguous 256B run
    {
        float4* sX4 = (float4*)sX;
        for (int i = tid; i < NROW * 16; i += 128) {
            int j = i >> 4, q = i & 15;
            const float4* src = (const float4*)(g_X + ((size_t)(j * EM1 + kw) * BB + b) * CC);
            sX4[i] = __ldcs(&src[q]);
        }
    }
    __syncthreads();
    // mix: thread owns coq = (tid&7)*2 (2 co), jg = tid>>3; j = jg + 16m
    {
        int coq = (tid & 7) * 2, jg = tid >> 3;
#pragma unroll
        for (int m = 0; m < 2; m++) {
            int j = jg + 16 * m;
            const float4* wrow = (const float4*)(g_Wt + ((size_t)(j * EM1 + kw)) * 1024
                                                 + half * 16 + coq);
            const float2* xrow = sX + j * CC;
            float r0 = 0.f, i0 = 0.f, r1 = 0.f, i1 = 0.f;
#pragma unroll 8
            for (int ci = 0; ci < 32; ci++) {
                float4 wv = __ldg(&wrow[ci * 16]);     // (w[co], w[co+1]); row stride 32 float2
                float2 xv = xrow[ci];
                r0 += xv.x * wv.x - xv.y * wv.y;
                i0 += xv.x * wv.y + xv.y * wv.x;
                r1 += xv.x * wv.z - xv.y * wv.w;
                i1 += xv.x * wv.w + xv.y * wv.z;
            }
            *(float4*)&sY[j * 16 + coq] = make_float4(r0, i0, r1, i1);
        }
    }
    __syncthreads();
    // fold Y -> P/Q
    for (int i = tid; i < EM1 * 16; i += 128) {
        int f = i >> 4, c = i & 15;
        float2 p, q;
        if (f == 0) { p = sY[c]; q = make_float2(0.f, 0.f); }
        else if (f == 16) {
            float2 yb = sY[16 * 16 + c];
            p = yb; q = make_float2(-yb.x, -yb.y);
        } else {
            float2 ya = sY[f * 16 + c], yb = sY[(32 - f) * 16 + c];
            p = make_float2(ya.x + yb.x, ya.y + yb.y);
            q = make_float2(ya.x - yb.x, ya.y - yb.y);
        }
        sP[i] = p; sQ[i] = q;
    }
    __syncthreads();
    int cig = tid & 3, hg = tid >> 2;     // hg 0..31
    int c0 = cig * 4;
    float EcR[2][4], EcI[2][4], OcR[2][4], OcI[2][4];
    float EsR[2][4], EsI[2][4], OsR[2][4], OsI[2][4];
    int hx[2];
#pragma unroll
    for (int m = 0; m < 2; m++) {
        hx[m] = 1 + hg + 32 * m;
#pragma unroll
        for (int c = 0; c < 4; c++) {
            EcR[m][c]=0; EcI[m][c]=0; OcR[m][c]=0; OcI[m][c]=0;
            EsR[m][c]=0; EsI[m][c]=0; OsR[m][c]=0; OsI[m][c]=0;
        }
    }
    int ti0 = 0, ti1 = 0;
#pragma unroll
    for (int f = 0; f < 17; f++) {
        float4 p01 = *(const float4*)&sP[f * 16 + c0];
        float4 p23 = *(const float4*)&sP[f * 16 + c0 + 2];
        float4 q01 = *(const float4*)&sQ[f * 16 + c0];
        float4 q23 = *(const float4*)&sQ[f * 16 + c0 + 2];
        float2 t0 = sT[ti0]; ti0 = (ti0 + hx[0]) & 255;
        float2 t1 = sT[ti1]; ti1 = (ti1 + hx[1]) & 255;
        if ((f & 1) == 0) {
            EcR[0][0] += p01.x*t0.x; EcI[0][0] += p01.y*t0.x; EsR[0][0] += q01.x*t0.y; EsI[0][0] += q01.y*t0.y;
            EcR[0][1] += p01.z*t0.x; EcI[0][1] += p01.w*t0.x; EsR[0][1] += q01.z*t0.y; EsI[0][1] += q01.w*t0.y;
            EcR[0][2] += p23.x*t0.x; EcI[0][2] += p23.y*t0.x; EsR[0][2] += q23.x*t0.y; EsI[0][2] += q23.y*t0.y;
            EcR[0][3] += p23.z*t0.x; EcI[0][3] += p23.w*t0.x; EsR[0][3] += q23.z*t0.y; EsI[0][3] += q23.w*t0.y;
            EcR[1][0] += p01.x*t1.x; EcI[1][0] += p01.y*t1.x; EsR[1][0] += q01.x*t1.y; EsI[1][0] += q01.y*t1.y;
            EcR[1][1] += p01.z*t1.x; EcI[1][1] += p01.w*t1.x; EsR[1][1] += q01.z*t1.y; EsI[1][1] += q01.w*t1.y;
            EcR[1][2] += p23.x*t1.x; EcI[1][2] += p23.y*t1.x; EsR[1][2] += q23.x*t1.y; EsI[1][2] += q23.y*t1.y;
            EcR[1][3] += p23.z*t1.x; EcI[1][3] += p23.w*t1.x; EsR[1][3] += q23.z*t1.y; EsI[1][3] += q23.w*t1.y;
        } else {
            OcR[0][0] += p01.x*t0.x; OcI[0][0] += p01.y*t0.x; OsR[0][0] += q01.x*t0.y; OsI[0][0] += q01.y*t0.y;
            OcR[0][1] += p01.z*t0.x; OcI[0][1] += p01.w*t0.x; OsR[0][1] += q01.z*t0.y; OsI[0][1] += q01.w*t0.y;
            OcR[0][2] += p23.x*t0.x; OcI[0][2] += p23.y*t0.x; OsR[0][2] += q23.x*t0.y; OsI[0][2] += q23.y*t0.y;
            OcR[0][3] += p23.z*t0.x; OcI[0][3] += p23.w*t0.x; OsR[0][3] += q23.z*t0.y; OsI[0][3] += q23.w*t0.y;
            OcR[1][0] += p01.x*t1.x; OcI[1][0] += p01.y*t1.x; OsR[1][0] += q01.x*t1.y; OsI[1][0] += q01.y*t1.y;
            OcR[1][1] += p01.z*t1.x; OcI[1][1] += p01.w*t1.x; OsR[1][1] += q01.z*t1.y; OsI[1][1] += q01.w*t1.y;
            OcR[1][2] += p23.x*t1.x; OcI[1][2] += p23.y*t1.x; OsR[1][2] += q23.x*t1.y; OsI[1][2] += q23.y*t1.y;
            OcR[1][3] += p23.z*t1.x; OcI[1][3] += p23.w*t1.x; OsR[1][3] += q23.z*t1.y; OsI[1][3] += q23.w*t1.y;
        }
    }
    int gc0 = half * 16 + c0;
#pragma unroll
    for (int m = 0; m < 2; m++) {
        int h = hx[m];
        float E1r[4], E1i[4], O1r[4], O1i[4], E2r[4], E2i[4], O2r[4], O2i[4];
#pragma unroll
        for (int c = 0; c < 4; c++) {
            E1r[c] = EcR[m][c] + OcR[m][c]; E1i[c] = EcI[m][c] + OcI[m][c];
            O1r[c] = EsR[m][c] + OsR[m][c]; O1i[c] = EsI[m][c] + OsI[m][c];
            E2r[c] = EcR[m][c] - OcR[m][c]; E2i[c] = EcI[m][c] - OcI[m][c];
            O2r[c] = -EsR[m][c] + OsR[m][c]; O2i[c] = -EsI[m][c] + OsI[m][c];
        }
        {
            int row = b * 256 + h;
            float4* d = (float4*)(g_Z + ((size_t)row * EM1 + kw) * CC + gc0);
            d[0] = make_float4(E1r[0]-O1i[0], E1i[0]+O1r[0], E1r[1]-O1i[1], E1i[1]+O1r[1]);
            d[1] = make_float4(E1r[2]-O1i[2], E1i[2]+O1r[2], E1r[3]-O1i[3], E1i[3]+O1r[3]);
            int row2 = b * 256 + (256 - h);
            float4* d2 = (float4*)(g_Z + ((size_t)row2 * EM1 + kw) * CC + gc0);
            d2[0] = make_float4(E1r[0]+O1i[0], E1i[0]-O1r[0], E1r[1]+O1i[1], E1i[1]-O1r[1]);
            d2[1] = make_float4(E1r[2]+O1i[2], E1i[2]-O1r[2], E1r[3]+O1i[3], E1i[3]-O1r[3]);
        }
        if (h != 64) {
            int row = b * 256 + (128 - h);
            float4* d = (float4*)(g_Z + ((size_t)row * EM1 + kw) * CC + gc0);
            d[0] = make_float4(E2r[0]-O2i[0], E2i[0]+O2r[0], E2r[1]-O2i[1], E2i[1]+O2r[1]);
            d[1] = make_float4(E2r[2]-O2i[2], E2i[2]+O2r[2], E2r[3]-O2i[3], E2i[3]+O2r[3]);
            int row2 = b * 256 + (128 + h);
            float4* d2 = (float4*)(g_Z + ((size_t)row2 * EM1 + kw) * CC + gc0);
            d2[0] = make_float4(E2r[0]+O2i[0], E2i[0]-O2r[0], E2r[1]+O2i[1], E2i[1]-O2r[1]);
            d2[1] = make_float4(E2r[2]+O2i[2], E2i[2]-O2r[2], E2r[3]+O2i[3], E2i[3]-O2r[3]);
        }
    }
    // h = 0 and h = 128
    if (tid < 32) {
        int c = tid & 15;
        bool is128 = tid >= 16;
        float2 acc = make_float2(0.f, 0.f);
#pragma unroll
        for (int f = 0; f < 17; f++) {
            float2 p = sP[f * 16 + c];
            float s = (is128 && (f & 1)) ? -1.0f : 1.0f;
            acc.x += s * p.x; acc.y += s * p.y;
        }
        int row = b * 256 + (is128 ? 128 : 0);
        g_Z[((size_t)row * EM1 + kw) * CC + half * 16 + c] = acc;
    }
}

// ---------------- K5: W-inverse (parity fold) + bias ----------------
__global__ void __launch_bounds__(128) k5_winv(const float* __restrict__ bias,
                                               float* __restrict__ out) {
    __shared__ __align__(16) float2 sZ[EM1 * 32];
    __shared__ float2 sT[256];
    __shared__ float sB[32];
    int row = blockIdx.x;
    int tid = threadIdx.x;
    const float4* src = (const float4*)(g_Z + (size_t)row * EM1 * CC);
    float4* sZ4 = (float4*)sZ;
    for (int i = tid; i < 272; i += 128) sZ4[i] = __ldcs(&src[i]);
    for (int i = tid; i < 256; i += 128) sT[i] = g_tw[i];
    if (tid < 32) sB[tid] = bias[tid];
    __syncthreads();
    int cig = tid & 7, wg = tid >> 3;     // wg 0..15
    int c0 = cig * 4;
    float base[4];
#pragma unroll
    for (int c = 0; c < 4; c++) base[c] = sZ[c0 + c].x + sB[c0 + c];
    float* orow = out + (size_t)row * 8192;
    float Pe[4][4], Po[4][4], Qe[4][4], Qo[4][4];
    int wv[4], idx[4];
#pragma unroll
    for (int m = 0; m < 4; m++) {
        wv[m] = 1 + wg + 16 * m;          // 1..64
        idx[m] = wv[m];
#pragma unroll
        for (int c = 0; c < 4; c++) { Pe[m][c]=0; Po[m][c]=0; Qe[m][c]=0; Qo[m][c]=0; }
    }
#pragma unroll
    for (int k = 1; k <= 16; k++) {
        float4 z01 = *(const float4*)&sZ[k * 32 + c0];
        float4 z23 = *(const float4*)&sZ[k * 32 + c0 + 2];
#pragma unroll
        for (int m = 0; m < 4; m++) {
            float2 t = sT[idx[m]];
            idx[m] = (idx[m] + wv[m]) & 255;
            if ((k & 1) == 0) {
                Pe[m][0] += z01.x * t.x; Qe[m][0] += z01.y * t.y;
                Pe[m][1] += z01.z * t.x; Qe[m][1] += z01.w * t.y;
                Pe[m][2] += z23.x * t.x; Qe[m][2] += z23.y * t.y;
                Pe[m][3] += z23.z * t.x; Qe[m][3] += z23.w * t.y;
            } else {
                Po[m][0] += z01.x * t.x; Qo[m][0] += z01.y * t.y;
                Po[m][1] += z01.z * t.x; Qo[m][1] += z01.w * t.y;
                Po[m][2] += z23.x * t.x; Qo[m][2] += z23.y * t.y;
                Po[m][3] += z23.z * t.x; Qo[m][3] += z23.w * t.y;
            }
        }
    }
#pragma unroll
    for (int m = 0; m < 4; m++) {
        int w = wv[m];
        float4 o1, o2;
        o1 = make_float4(base[0] + 2.0f*(Pe[m][0]+Po[m][0]-Qe[m][0]-Qo[m][0]),
                         base[1] + 2.0f*(Pe[m][1]+Po[m][1]-Qe[m][1]-Qo[m][1]),
                         base[2] + 2.0f*(Pe[m][2]+Po[m][2]-Qe[m][2]-Qo[m][2]),
                         base[3] + 2.0f*(Pe[m][3]+Po[m][3]-Qe[m][3]-Qo[m][3]));
        o2 = make_float4(base[0] + 2.0f*(Pe[m][0]+Po[m][0]+Qe[m][0]+Qo[m][0]),
                         base[1] + 2.0f*(Pe[m][1]+Po[m][1]+Qe[m][1]+Qo[m][1]),
                         base[2] + 2.0f*(Pe[m][2]+Po[m][2]+Qe[m][2]+Qo[m][2]),
                         base[3] + 2.0f*(Pe[m][3]+Po[m][3]+Qe[m][3]+Qo[m][3]));
        __stcs((float4*)(orow + w * 32 + c0), o1);
        __stcs((float4*)(orow + (256 - w) * 32 + c0), o2);
        if (w != 64) {
            float4 o3, o4;
            o3 = make_float4(base[0] + 2.0f*(Pe[m][0]-Po[m][0]+Qe[m][0]-Qo[m][0]),
                             base[1] + 2.0f*(Pe[m][1]-Po[m][1]+Qe[m][1]-Qo[m][1]),
                             base[2] + 2.0f*(Pe[m][2]-Po[m][2]+Qe[m][2]-Qo[m][2]),
                             base[3] + 2.0f*(Pe[m][3]-Po[m][3]+Qe[m][3]-Qo[m][3]));
            o4 = make_float4(base[0] + 2.0f*(Pe[m][0]-Po[m][0]-Qe[m][0]+Qo[m][0]),
                             base[1] + 2.0f*(Pe[m][1]-Po[m][1]-Qe[m][1]+Qo[m][1]),
                             base[2] + 2.0f*(Pe[m][2]-Po[m][2]-Qe[m][2]+Qo[m][2]),
                             base[3] + 2.0f*(Pe[m][3]-Po[m][3]-Qe[m][3]+Qo[m][3]));
            __stcs((float4*)(orow + (128 - w) * 32 + c0), o3);
            __stcs((float4*)(orow + (128 + w) * 32 + c0), o4);
        }
    }
    // w = 0 and w = 128
    if (tid < 64) {
        int c = tid & 31;
        bool is128 = tid >= 32;
        float acc = 0.f;
#pragma unroll
        for (int k = 1; k <= 16; k++) {
            float zr = sZ[k * 32 + c].x;
            acc += (is128 && (k & 1)) ? -zr : zr;
        }
        __stcs(&orow[(is128 ? 128 * 32 : 0) + c], sZ[c].x + sB[c] + 2.0f * acc);
    }
}

extern "C" void kernel_launch(void* const* d_in, const int* in_sizes, int n_in,
                              void* d_out, int out_size) {
    const float* x    = (const float*)d_in[0];
    const float* w1r  = (const float*)d_in[1];
    const float* w1i  = (const float*)d_in[2];
    const float* w2r  = (const float*)d_in[3];
    const float* w2i  = (const float*)d_in[4];
    const float* bias = (const float*)d_in[5];
    float* out = (float*)d_out;

    kt_w<<<1088, 256>>>(w1r, w1i, w2r, w2i);
    k1_wdft<<<BB * HH, 128>>>(x);
    k2_hdft<<<BB * EM1 * 2, 128>>>();
    k34_mixhinv<<<BB * EM1 * 2, 128>>>();
    k5_winv<<<BB * HH, 128>>>(bias, out);
}